// round 1
// baseline (speedup 1.0000x reference)
#include <cuda_runtime.h>
#include <math.h>

#define N_NODES 50000
#define T_STEPS 24
#define D_IN 64
#define E_EDGES 800000
#define NT_ROWS (N_NODES * T_STEPS)

// ---------------- scratch (device globals; no runtime allocation) ----------
__device__ float g_sum[64];
__device__ float g_sumsq[64];
__device__ float g_a[64];
__device__ float g_bsh[64];
__device__ float g_W0s[64 * 64];
__device__ float g_bvec0[64];
__device__ float g_zero64[64];          // stays zero (bss)
__device__ float g_WihT[64 * 256];
__device__ float g_WhhT[64 * 256];
__device__ float g_gbias[256];
__device__ float g_outnorm[N_NODES];
__device__ float g_innorm[N_NODES];
__device__ int   g_degout[N_NODES];
__device__ int   g_degin[N_NODES];
__device__ int   g_rowptr[N_NODES + 1];
__device__ int   g_cursor[N_NODES];
__device__ int   g_csrsrc[E_EDGES];
__device__ float g_bufM[N_NODES * 64];
__device__ float g_bufY[N_NODES * 64];
__device__ float g_hst[N_NODES * 64];
__device__ float g_cst[N_NODES * 64];

__device__ __forceinline__ float gelu_f(float x) {
    return 0.5f * x * (1.0f + erff(x * 0.70710678118654752440f));
}
__device__ __forceinline__ float sig_f(float x) {
    return 1.0f / (1.0f + expf(-x));
}

// ---------------- init: zero output + accumulators -------------------------
__global__ void k_init(float* out, int out_n) {
    int i = blockIdx.x * blockDim.x + threadIdx.x;
    int stride = gridDim.x * blockDim.x;
    for (int j = i; j < out_n; j += stride) out[j] = 0.0f;
    for (int j = i; j < N_NODES; j += stride) { g_degout[j] = 0; g_degin[j] = 0; }
    if (i < 64) { g_sum[i] = 0.0f; g_sumsq[i] = 0.0f; }
}

// ---------------- BN stats (sum / sumsq per channel) -----------------------
__global__ void k_bnstats(const float4* __restrict__ h4) {
    __shared__ float ss[64], sq[64];
    int tid = threadIdx.x;
    if (tid < 64) { ss[tid] = 0.0f; sq[tid] = 0.0f; }
    __syncthreads();
    const int total4 = NT_ROWS * 16;   // 64 floats per row / 4
    float4 s = make_float4(0, 0, 0, 0);
    float4 q = make_float4(0, 0, 0, 0);
    for (int i = blockIdx.x * blockDim.x + tid; i < total4; i += gridDim.x * blockDim.x) {
        float4 v = h4[i];
        s.x += v.x; s.y += v.y; s.z += v.z; s.w += v.w;
        q.x += v.x * v.x; q.y += v.y * v.y; q.z += v.z * v.z; q.w += v.w * v.w;
    }
    int c = (tid & 15) * 4;  // stride is multiple of 16 float4s -> channel quad fixed
    atomicAdd(&ss[c + 0], s.x); atomicAdd(&ss[c + 1], s.y);
    atomicAdd(&ss[c + 2], s.z); atomicAdd(&ss[c + 3], s.w);
    atomicAdd(&sq[c + 0], q.x); atomicAdd(&sq[c + 1], q.y);
    atomicAdd(&sq[c + 2], q.z); atomicAdd(&sq[c + 3], q.w);
    __syncthreads();
    if (tid < 64) {
        atomicAdd(&g_sum[tid], ss[tid]);
        atomicAdd(&g_sumsq[tid], sq[tid]);
    }
}

// ---------------- finalize BN + fold into weights --------------------------
__global__ void k_prep(const float* __restrict__ gamma, const float* __restrict__ beta,
                       const float* __restrict__ W0,
                       const float* __restrict__ Wih, const float* __restrict__ Whh,
                       const float* __restrict__ bih, const float* __restrict__ bhh) {
    __shared__ float sa[64], sb[64];
    int tid = threadIdx.x;  // 256 threads, one block
    if (tid < 64) {
        float mu  = g_sum[tid]   * (1.0f / (float)NT_ROWS);
        float var = g_sumsq[tid] * (1.0f / (float)NT_ROWS) - mu * mu;
        float a = gamma[tid] * rsqrtf(var + 1e-5f);
        sa[tid] = a;
        sb[tid] = beta[tid] - mu * a;
        g_a[tid] = a; g_bsh[tid] = sb[tid];
    }
    __syncthreads();
    // W0' = diag(a) @ W0
    for (int idx = tid; idx < 4096; idx += 256) {
        int k = idx >> 6;
        g_W0s[idx] = sa[k] * W0[idx];
    }
    // bvec0 = bsh @ W0
    if (tid < 64) {
        float acc = 0.0f;
        for (int k = 0; k < 64; k++) acc += sb[k] * W0[k * 64 + tid];
        g_bvec0[tid] = acc;
    }
    // WihT'[k][g] = a[k]*Wih[g][k],  WhhT[k][g] = Whh[g][k]
    for (int idx = tid; idx < 16384; idx += 256) {
        int k = idx >> 8, g = idx & 255;
        g_WihT[idx] = sa[k] * Wih[g * 64 + k];
        g_WhhT[idx] = Whh[g * 64 + k];
    }
    // gate bias = bih + bhh + bsh @ Wih^T
    {
        float acc = bih[tid] + bhh[tid];
        for (int k = 0; k < 64; k++) acc += sb[k] * Wih[tid * 64 + k];
        g_gbias[tid] = acc;
    }
}

// ---------------- degrees / norms / CSR -------------------------------------
__global__ void k_deg(const int* __restrict__ src, const int* __restrict__ dst) {
    for (int e = blockIdx.x * blockDim.x + threadIdx.x; e < E_EDGES;
         e += gridDim.x * blockDim.x) {
        atomicAdd(&g_degout[src[e]], 1);
        atomicAdd(&g_degin[dst[e]], 1);
    }
}

__global__ void k_norm() {
    for (int n = blockIdx.x * blockDim.x + threadIdx.x; n < N_NODES;
         n += gridDim.x * blockDim.x) {
        g_outnorm[n] = rsqrtf(fmaxf((float)g_degout[n], 1.0f));
        g_innorm[n]  = rsqrtf(fmaxf((float)g_degin[n], 1.0f));
    }
}

// single-block exclusive scan of in-degrees -> rowptr (+ cursor copy)
__global__ void k_scan() {
    __shared__ int s[1024];
    const int CH = 49;  // 1024*49 >= 50001
    int tid = threadIdx.x;
    int base = tid * CH;
    int tot = 0;
    for (int i = 0; i < CH; i++) {
        int idx = base + i;
        if (idx < N_NODES) tot += g_degin[idx];
    }
    s[tid] = tot;
    __syncthreads();
    for (int off = 1; off < 1024; off <<= 1) {
        int v = (tid >= off) ? s[tid - off] : 0;
        __syncthreads();
        s[tid] += v;
        __syncthreads();
    }
    int run = (tid > 0) ? s[tid - 1] : 0;
    for (int i = 0; i < CH; i++) {
        int idx = base + i;
        if (idx < N_NODES) {
            g_rowptr[idx] = run;
            g_cursor[idx] = run;
            run += g_degin[idx];
        } else if (idx == N_NODES) {
            g_rowptr[idx] = run;
        }
    }
}

__global__ void k_csr(const int* __restrict__ src, const int* __restrict__ dst) {
    for (int e = blockIdx.x * blockDim.x + threadIdx.x; e < E_EDGES;
         e += gridDim.x * blockDim.x) {
        int pos = atomicAdd(&g_cursor[dst[e]], 1);
        g_csrsrc[pos] = src[e];
    }
}

// ---------------- 64x64 GEMM: out[n] = out_norm[n] * (X[n] @ W + bias) ------
__global__ void __launch_bounds__(256) k_gemm64(
    const float* __restrict__ X, int xstride,
    const float* __restrict__ W, const float* __restrict__ bias,
    float* __restrict__ out) {
    __shared__ float xs[64][65];
    __shared__ float ws[64][64];
    __shared__ float sbias[64];
    int tid = threadIdx.x;
    int n0 = blockIdx.x * 64;

    for (int idx = tid; idx < 64 * 16; idx += 256) {
        int r = idx >> 4, q = idx & 15;
        float4 v = *(const float4*)&W[r * 64 + q * 4];
        *(float4*)&ws[r][q * 4] = v;
    }
    if (tid < 64) sbias[tid] = bias[tid];
    for (int idx = tid; idx < 64 * 16; idx += 256) {
        int r = idx >> 4, q = idx & 15;
        int n = n0 + r;
        if (n < N_NODES) {
            float4 v = *(const float4*)&X[n * xstride + q * 4];
            xs[r][q * 4 + 0] = v.x; xs[r][q * 4 + 1] = v.y;
            xs[r][q * 4 + 2] = v.z; xs[r][q * 4 + 3] = v.w;
        }
    }
    __syncthreads();

    int r0 = (tid >> 4) * 4;
    int c0 = (tid & 15) * 4;
    float acc[4][4] = {};
#pragma unroll 8
    for (int k = 0; k < 64; k++) {
        float4 w = *(float4*)&ws[k][c0];
#pragma unroll
        for (int i = 0; i < 4; i++) {
            float xv = xs[r0 + i][k];
            acc[i][0] += xv * w.x; acc[i][1] += xv * w.y;
            acc[i][2] += xv * w.z; acc[i][3] += xv * w.w;
        }
    }
#pragma unroll
    for (int i = 0; i < 4; i++) {
        int n = n0 + r0 + i;
        if (n < N_NODES) {
            float sc = g_outnorm[n];
            float4 o;
            o.x = sc * (acc[i][0] + sbias[c0 + 0]);
            o.y = sc * (acc[i][1] + sbias[c0 + 1]);
            o.z = sc * (acc[i][2] + sbias[c0 + 2]);
            o.w = sc * (acc[i][3] + sbias[c0 + 3]);
            *(float4*)&out[n * 64 + c0] = o;
        }
    }
}

// ---------------- CSR gather + gelu (mode0: write Y; mode1: mean -> hs) -----
__global__ void __launch_bounds__(256) k_gather(
    const float* __restrict__ M, const float* __restrict__ bias,
    float* __restrict__ outY, float* __restrict__ hsout, int mode) {
    int lane = threadIdx.x & 31;
    int warp = (blockIdx.x * blockDim.x + threadIdx.x) >> 5;
    int nwarps = (gridDim.x * blockDim.x) >> 5;
    float b0 = bias[2 * lane], b1 = bias[2 * lane + 1];
    float acc0t = 0.0f, acc1t = 0.0f;

    for (int v = warp; v < N_NODES; v += nwarps) {
        int s = g_rowptr[v], e = g_rowptr[v + 1];
        float a0 = 0.0f, a1 = 0.0f;
        int i = s;
        for (; i + 4 <= e; i += 4) {
            int u0 = g_csrsrc[i + 0];
            int u1 = g_csrsrc[i + 1];
            int u2 = g_csrsrc[i + 2];
            int u3 = g_csrsrc[i + 3];
            float2 m0 = *(const float2*)&M[u0 * 64 + lane * 2];
            float2 m1 = *(const float2*)&M[u1 * 64 + lane * 2];
            float2 m2 = *(const float2*)&M[u2 * 64 + lane * 2];
            float2 m3 = *(const float2*)&M[u3 * 64 + lane * 2];
            a0 += (m0.x + m1.x) + (m2.x + m3.x);
            a1 += (m0.y + m1.y) + (m2.y + m3.y);
        }
        for (; i < e; i++) {
            int u = g_csrsrc[i];
            float2 m = *(const float2*)&M[u * 64 + lane * 2];
            a0 += m.x; a1 += m.y;
        }
        float inn = g_innorm[v];
        float y0 = gelu_f(a0 * inn + b0);
        float y1 = gelu_f(a1 * inn + b1);
        if (mode == 0) {
            *(float2*)&outY[v * 64 + lane * 2] = make_float2(y0, y1);
        } else {
            acc0t += y0; acc1t += y1;
        }
    }
    if (mode == 1) {
        __shared__ float red[64];
        if (threadIdx.x < 64) red[threadIdx.x] = 0.0f;
        __syncthreads();
        atomicAdd(&red[2 * lane + 0], acc0t);
        atomicAdd(&red[2 * lane + 1], acc1t);
        __syncthreads();
        if (threadIdx.x < 64)
            atomicAdd(&hsout[threadIdx.x], red[threadIdx.x] * (1.0f / (float)N_NODES));
    }
}

// ---------------- fused LSTM step: gates = x@Wih'^T + h@Whh^T + b -----------
// 8 nodes per warp; all weights in dynamic smem (128 KB); fp32 FMA-bound.
#define LSTM_SMEM_FLOATS (16384 + 16384 + 256 + 8 * 8 * 128)
__global__ void __launch_bounds__(256, 1) k_lstm(
    const float* __restrict__ h_all, int t, float* __restrict__ out_ht) {
    extern __shared__ float sm[];
    float* sWi = sm;                 // [64][256]
    float* sWh = sm + 16384;         // [64][256]
    float* sB  = sm + 32768;         // [256]
    float* sXH = sm + 33024;         // 8 warps * (8 nodes * 64 x  + 8 nodes * 64 h)

    int tid = threadIdx.x, w = tid >> 5, lane = tid & 31;
    for (int i = tid; i < 4096; i += 256) {
        ((float4*)sWi)[i] = ((const float4*)g_WihT)[i];
        ((float4*)sWh)[i] = ((const float4*)g_WhhT)[i];
    }
    sB[tid] = g_gbias[tid];
    __syncthreads();

    float* myX = sXH + w * 1024;
    float* myH = myX + 512;
    const int NCH = (N_NODES + 63) / 64;
    const float invT = 1.0f / (float)T_STEPS;

    for (int ch = blockIdx.x; ch < NCH; ch += gridDim.x) {
        int n0 = ch * 64 + w * 8;
        // stage x and hprev for 8 nodes
        for (int j = lane; j < 128; j += 32) {
            int i = j >> 4, q = j & 15;
            int n = n0 + i;
            float4 xv = make_float4(0, 0, 0, 0), hv = make_float4(0, 0, 0, 0);
            if (n < N_NODES) {
                xv = *(const float4*)&h_all[(n * T_STEPS + t) * 64 + q * 4];
                if (t > 0) hv = *(const float4*)&g_hst[n * 64 + q * 4];
            }
            *(float4*)&myX[i * 64 + q * 4] = xv;
            *(float4*)&myH[i * 64 + q * 4] = hv;
        }
        __syncwarp();

        float acc[8][8];
#pragma unroll
        for (int i = 0; i < 8; i++)
#pragma unroll
            for (int r = 0; r < 8; r++) acc[i][r] = 0.0f;

#pragma unroll 2
        for (int k = 0; k < 64; k++) {
            float wi[8], wh[8];
#pragma unroll
            for (int r = 0; r < 8; r++) {
                wi[r] = sWi[k * 256 + lane + 32 * r];
                wh[r] = sWh[k * 256 + lane + 32 * r];
            }
#pragma unroll
            for (int i = 0; i < 8; i++) {
                float xk = myX[i * 64 + k];
                float hk = myH[i * 64 + k];
#pragma unroll
                for (int r = 0; r < 8; r++) {
                    acc[i][r] += xk * wi[r];
                    acc[i][r] += hk * wh[r];
                }
            }
        }

#pragma unroll
        for (int i = 0; i < 8; i++) {
            int n = n0 + i;
            if (n >= N_NODES) continue;
            float gi0 = acc[i][0] + sB[lane +   0], gi1 = acc[i][1] + sB[lane +  32];
            float gf0 = acc[i][2] + sB[lane +  64], gf1 = acc[i][3] + sB[lane +  96];
            float gg0 = acc[i][4] + sB[lane + 128], gg1 = acc[i][5] + sB[lane + 160];
            float go0 = acc[i][6] + sB[lane + 192], go1 = acc[i][7] + sB[lane + 224];
            float c0p = 0.0f, c1p = 0.0f;
            if (t > 0) {
                c0p = g_cst[n * 64 + lane];
                c1p = g_cst[n * 64 + lane + 32];
            }
            float c0 = sig_f(gf0) * c0p + sig_f(gi0) * tanhf(gg0);
            float c1 = sig_f(gf1) * c1p + sig_f(gi1) * tanhf(gg1);
            float h0 = sig_f(go0) * tanhf(c0);
            float h1 = sig_f(go1) * tanhf(c1);
            g_cst[n * 64 + lane]      = c0;
            g_cst[n * 64 + lane + 32] = c1;
            g_hst[n * 64 + lane]      = h0;
            g_hst[n * 64 + lane + 32] = h1;
            out_ht[n * 64 + lane]      += h0 * invT;
            out_ht[n * 64 + lane + 32] += h1 * invT;
        }
        __syncwarp();
    }
}

// ---------------- launch ----------------------------------------------------
extern "C" void kernel_launch(void* const* d_in, const int* in_sizes, int n_in,
                              void* d_out, int out_size) {
    const float* h     = (const float*)d_in[0];
    const int*   src   = (const int*)d_in[1];
    const int*   dst   = (const int*)d_in[2];
    const float* gamma = (const float*)d_in[3];
    const float* beta  = (const float*)d_in[4];
    const float* W0    = (const float*)d_in[5];
    const float* b0    = (const float*)d_in[6];
    const float* W1    = (const float*)d_in[7];
    const float* b1    = (const float*)d_in[8];
    const float* Wih   = (const float*)d_in[9];
    const float* Whh   = (const float*)d_in[10];
    const float* bih   = (const float*)d_in[11];
    const float* bhh   = (const float*)d_in[12];
    float* out = (float*)d_out;

    (void)in_sizes; (void)n_in;

    const int lstm_smem = LSTM_SMEM_FLOATS * (int)sizeof(float);
    cudaFuncSetAttribute(k_lstm, cudaFuncAttributeMaxDynamicSharedMemorySize, lstm_smem);

    float *pW0s, *pbvec0, *pzero, *pbufM, *pbufY;
    cudaGetSymbolAddress((void**)&pW0s,   g_W0s);
    cudaGetSymbolAddress((void**)&pbvec0, g_bvec0);
    cudaGetSymbolAddress((void**)&pzero,  g_zero64);
    cudaGetSymbolAddress((void**)&pbufM,  g_bufM);
    cudaGetSymbolAddress((void**)&pbufY,  g_bufY);

    k_init<<<512, 256>>>(out, out_size);
    k_bnstats<<<1184, 256>>>((const float4*)h);
    k_deg<<<800, 256>>>(src, dst);
    k_prep<<<1, 256>>>(gamma, beta, W0, Wih, Whh, bih, bhh);
    k_norm<<<128, 256>>>();
    k_scan<<<1, 1024>>>();
    k_csr<<<800, 256>>>(src, dst);

    const int gemm_blocks = (N_NODES + 63) / 64;
    for (int t = 0; t < T_STEPS; t++) {
        // spatial: conv1 -> gather -> conv2 -> gather+mean
        k_gemm64<<<gemm_blocks, 256>>>(h + t * 64, T_STEPS * 64, pW0s, pbvec0, pbufM);
        k_gather<<<640, 256>>>(pbufM, b0, pbufY, nullptr, 0);
        k_gemm64<<<gemm_blocks, 256>>>(pbufY, 64, W1, pzero, pbufM);
        k_gather<<<296, 256>>>(pbufM, b1, nullptr, out + t * 64, 1);
        // temporal: fused LSTM step
        k_lstm<<<148, 256, lstm_smem>>>(h, t, out + 1536);
    }
}

// round 2
// speedup vs baseline: 1.5444x; 1.5444x over previous
#include <cuda_runtime.h>
#include <math.h>

#define N_NODES 50000
#define T_STEPS 24
#define D_IN 64
#define E_EDGES 800000
#define NT_ROWS (N_NODES * T_STEPS)

typedef unsigned long long ull;

// ---------------- f32x2 packed helpers --------------------------------------
__device__ __forceinline__ ull ffma2(ull a, ull b, ull c) {
    ull d;
    asm("fma.rn.f32x2 %0, %1, %2, %3;" : "=l"(d) : "l"(a), "l"(b), "l"(c));
    return d;
}
__device__ __forceinline__ ull dup2f(float x) {
    ull r;
    asm("mov.b64 %0, {%1, %1};" : "=l"(r) : "f"(x));
    return r;
}
__device__ __forceinline__ ull pack2f(float x, float y) {
    ull r;
    asm("mov.b64 %0, {%1, %2};" : "=l"(r) : "f"(x), "f"(y));
    return r;
}
__device__ __forceinline__ float2 unpack2(ull v) {
    float2 r;
    asm("mov.b64 {%0, %1}, %2;" : "=f"(r.x), "=f"(r.y) : "l"(v));
    return r;
}

// ---------------- scratch (device globals; no runtime allocation) ----------
__device__ float g_sum[64];
__device__ float g_sumsq[64];
__device__ float g_a[64];
__device__ float g_bsh[64];
__device__ float g_W0s[64 * 64];
__device__ float g_bvec0[64];
__device__ float g_zero64[64];          // stays zero (bss)
__device__ ull   g_Wi2[64 * 128];       // packed (a*Wih) pairs: [k][j*32+l]
__device__ ull   g_Wh2[64 * 128];       // packed Whh pairs
__device__ ull   g_b2[128];             // packed gate bias pairs
__device__ float g_outnorm[N_NODES];
__device__ float g_innorm[N_NODES];
__device__ int   g_degout[N_NODES];
__device__ int   g_degin[N_NODES];
__device__ int   g_rowptr[N_NODES + 1];
__device__ int   g_cursor[N_NODES];
__device__ int   g_csrsrc[E_EDGES];
__device__ float g_bufM[N_NODES * 64];
__device__ float g_bufY[N_NODES * 64];
__device__ int   g_wq;

__device__ __forceinline__ float gelu_f(float x) {
    return 0.5f * x * (1.0f + erff(x * 0.70710678118654752440f));
}
__device__ __forceinline__ float sig_f(float x) {
    return 1.0f / (1.0f + expf(-x));
}

// ---------------- init: zero output + accumulators -------------------------
__global__ void k_init(float* out, int out_n) {
    int i = blockIdx.x * blockDim.x + threadIdx.x;
    int stride = gridDim.x * blockDim.x;
    for (int j = i; j < out_n; j += stride) out[j] = 0.0f;
    for (int j = i; j < N_NODES; j += stride) { g_degout[j] = 0; g_degin[j] = 0; }
    if (i < 64) { g_sum[i] = 0.0f; g_sumsq[i] = 0.0f; }
    if (i == 0) g_wq = 0;
}

// ---------------- BN stats (sum / sumsq per channel) -----------------------
__global__ void k_bnstats(const float4* __restrict__ h4) {
    __shared__ float ss[64], sq[64];
    int tid = threadIdx.x;
    if (tid < 64) { ss[tid] = 0.0f; sq[tid] = 0.0f; }
    __syncthreads();
    const int total4 = NT_ROWS * 16;
    float4 s = make_float4(0, 0, 0, 0);
    float4 q = make_float4(0, 0, 0, 0);
    for (int i = blockIdx.x * blockDim.x + tid; i < total4; i += gridDim.x * blockDim.x) {
        float4 v = h4[i];
        s.x += v.x; s.y += v.y; s.z += v.z; s.w += v.w;
        q.x += v.x * v.x; q.y += v.y * v.y; q.z += v.z * v.z; q.w += v.w * v.w;
    }
    int c = (tid & 15) * 4;
    atomicAdd(&ss[c + 0], s.x); atomicAdd(&ss[c + 1], s.y);
    atomicAdd(&ss[c + 2], s.z); atomicAdd(&ss[c + 3], s.w);
    atomicAdd(&sq[c + 0], q.x); atomicAdd(&sq[c + 1], q.y);
    atomicAdd(&sq[c + 2], q.z); atomicAdd(&sq[c + 3], q.w);
    __syncthreads();
    if (tid < 64) {
        atomicAdd(&g_sum[tid], ss[tid]);
        atomicAdd(&g_sumsq[tid], sq[tid]);
    }
}

// ---------------- BN finalize + fold into W0 --------------------------------
__global__ void k_prep1(const float* __restrict__ gamma, const float* __restrict__ beta,
                        const float* __restrict__ W0) {
    __shared__ float sa[64], sb[64];
    int tid = threadIdx.x;  // 256 threads
    if (tid < 64) {
        float mu  = g_sum[tid]   * (1.0f / (float)NT_ROWS);
        float var = g_sumsq[tid] * (1.0f / (float)NT_ROWS) - mu * mu;
        float a = gamma[tid] * rsqrtf(var + 1e-5f);
        sa[tid] = a;
        sb[tid] = beta[tid] - mu * a;
        g_a[tid] = a; g_bsh[tid] = sb[tid];
    }
    __syncthreads();
    for (int idx = tid; idx < 4096; idx += 256) {
        int k = idx >> 6;
        g_W0s[idx] = sa[k] * W0[idx];
    }
    if (tid < 64) {
        float acc = 0.0f;
        for (int k = 0; k < 64; k++) acc += sb[k] * W0[k * 64 + tid];
        g_bvec0[tid] = acc;
    }
}

// ---------------- pack LSTM weights as f32x2 pairs ---------------------------
__global__ void k_prep2(const float* __restrict__ Wih, const float* __restrict__ Whh) {
    int idx = blockIdx.x * blockDim.x + threadIdx.x;   // 0..8191
    if (idx >= 8192) return;
    int k = idx >> 7, r = idx & 127;
    int j = r >> 5, l = r & 31;
    int gA = j * 64 + l, gB = gA + 32;
    float a = g_a[k];
    g_Wi2[idx] = pack2f(a * Wih[gA * 64 + k], a * Wih[gB * 64 + k]);
    g_Wh2[idx] = pack2f(Whh[gA * 64 + k], Whh[gB * 64 + k]);
}

__global__ void k_prep3(const float* __restrict__ Wih,
                        const float* __restrict__ bih, const float* __restrict__ bhh) {
    __shared__ float sgb[256];
    int g = threadIdx.x;  // 256 threads
    float acc = bih[g] + bhh[g];
    for (int k = 0; k < 64; k++) acc += g_bsh[k] * Wih[g * 64 + k];
    sgb[g] = acc;
    __syncthreads();
    if (g < 128) {
        int j = g >> 5, l = g & 31;
        g_b2[g] = pack2f(sgb[j * 64 + l], sgb[j * 64 + 32 + l]);
    }
}

// ---------------- degrees / norms / CSR -------------------------------------
__global__ void k_deg(const int* __restrict__ src, const int* __restrict__ dst) {
    for (int e = blockIdx.x * blockDim.x + threadIdx.x; e < E_EDGES;
         e += gridDim.x * blockDim.x) {
        atomicAdd(&g_degout[src[e]], 1);
        atomicAdd(&g_degin[dst[e]], 1);
    }
}

__global__ void k_norm() {
    for (int n = blockIdx.x * blockDim.x + threadIdx.x; n < N_NODES;
         n += gridDim.x * blockDim.x) {
        g_outnorm[n] = rsqrtf(fmaxf((float)g_degout[n], 1.0f));
        g_innorm[n]  = rsqrtf(fmaxf((float)g_degin[n], 1.0f));
    }
}

__global__ void k_scan() {
    __shared__ int s[1024];
    const int CH = 49;
    int tid = threadIdx.x;
    int base = tid * CH;
    int tot = 0;
    for (int i = 0; i < CH; i++) {
        int idx = base + i;
        if (idx < N_NODES) tot += g_degin[idx];
    }
    s[tid] = tot;
    __syncthreads();
    for (int off = 1; off < 1024; off <<= 1) {
        int v = (tid >= off) ? s[tid - off] : 0;
        __syncthreads();
        s[tid] += v;
        __syncthreads();
    }
    int run = (tid > 0) ? s[tid - 1] : 0;
    for (int i = 0; i < CH; i++) {
        int idx = base + i;
        if (idx < N_NODES) {
            g_rowptr[idx] = run;
            g_cursor[idx] = run;
            run += g_degin[idx];
        } else if (idx == N_NODES) {
            g_rowptr[idx] = run;
        }
    }
}

__global__ void k_csr(const int* __restrict__ src, const int* __restrict__ dst) {
    for (int e = blockIdx.x * blockDim.x + threadIdx.x; e < E_EDGES;
         e += gridDim.x * blockDim.x) {
        int pos = atomicAdd(&g_cursor[dst[e]], 1);
        g_csrsrc[pos] = src[e];
    }
}

// ---------------- 64x64 GEMM (f32x2): out[n] = outnorm[n]*(X[n]@W + bias) ---
__global__ void __launch_bounds__(256, 6) k_gemm64(
    const float* __restrict__ X, int xstride,
    const float* __restrict__ W, const float* __restrict__ bias,
    float* __restrict__ out) {
    __shared__ __align__(16) float xs[64][64];
    __shared__ __align__(16) float ws[64][64];
    __shared__ float sbias[64];
    int tid = threadIdx.x;
    int n0 = blockIdx.x * 64;

    for (int idx = tid; idx < 64 * 16; idx += 256) {
        int r = idx >> 4, q = idx & 15;
        *(float4*)&ws[r][q * 4] = *(const float4*)&W[r * 64 + q * 4];
    }
    if (tid < 64) sbias[tid] = bias[tid];
    for (int idx = tid; idx < 64 * 16; idx += 256) {
        int r = idx >> 4, q = idx & 15;
        int n = n0 + r;
        if (n < N_NODES)
            *(float4*)&xs[r][q * 4] = *(const float4*)&X[n * xstride + q * 4];
    }
    __syncthreads();

    int r0 = (tid >> 4) * 4;
    int c0 = (tid & 15) * 4;
    ull acc[4][2] = {};
#pragma unroll 8
    for (int k = 0; k < 64; k++) {
        ulonglong2 wp = *(ulonglong2*)&ws[k][c0];
#pragma unroll
        for (int i = 0; i < 4; i++) {
            ull x2 = dup2f(xs[r0 + i][k]);
            acc[i][0] = ffma2(x2, wp.x, acc[i][0]);
            acc[i][1] = ffma2(x2, wp.y, acc[i][1]);
        }
    }
#pragma unroll
    for (int i = 0; i < 4; i++) {
        int n = n0 + r0 + i;
        if (n < N_NODES) {
            float sc = g_outnorm[n];
            float2 p0 = unpack2(acc[i][0]);
            float2 p1 = unpack2(acc[i][1]);
            float4 o;
            o.x = sc * (p0.x + sbias[c0 + 0]);
            o.y = sc * (p0.y + sbias[c0 + 1]);
            o.z = sc * (p1.x + sbias[c0 + 2]);
            o.w = sc * (p1.y + sbias[c0 + 3]);
            *(float4*)&out[n * 64 + c0] = o;
        }
    }
}

// ---------------- CSR gather + gelu (mode0: write Y; mode1: mean -> hs) -----
__global__ void __launch_bounds__(256, 6) k_gather(
    const float* __restrict__ M, const float* __restrict__ bias,
    float* __restrict__ outY, float* __restrict__ hsout, int mode) {
    int lane = threadIdx.x & 31;
    int warp = (blockIdx.x * blockDim.x + threadIdx.x) >> 5;
    int nwarps = (gridDim.x * blockDim.x) >> 5;
    float b0 = bias[2 * lane], b1 = bias[2 * lane + 1];
    float acc0t = 0.0f, acc1t = 0.0f;

    for (int v = warp; v < N_NODES; v += nwarps) {
        int s = g_rowptr[v], e = g_rowptr[v + 1];
        float a0 = 0.0f, a1 = 0.0f;
        int i = s;
        for (; i + 4 <= e; i += 4) {
            int u0 = g_csrsrc[i + 0];
            int u1 = g_csrsrc[i + 1];
            int u2 = g_csrsrc[i + 2];
            int u3 = g_csrsrc[i + 3];
            float2 m0 = *(const float2*)&M[u0 * 64 + lane * 2];
            float2 m1 = *(const float2*)&M[u1 * 64 + lane * 2];
            float2 m2 = *(const float2*)&M[u2 * 64 + lane * 2];
            float2 m3 = *(const float2*)&M[u3 * 64 + lane * 2];
            a0 += (m0.x + m1.x) + (m2.x + m3.x);
            a1 += (m0.y + m1.y) + (m2.y + m3.y);
        }
        for (; i < e; i++) {
            int u = g_csrsrc[i];
            float2 m = *(const float2*)&M[u * 64 + lane * 2];
            a0 += m.x; a1 += m.y;
        }
        float inn = g_innorm[v];
        float y0 = gelu_f(a0 * inn + b0);
        float y1 = gelu_f(a1 * inn + b1);
        if (mode == 0) {
            *(float2*)&outY[v * 64 + lane * 2] = make_float2(y0, y1);
        } else {
            acc0t += y0; acc1t += y1;
        }
    }
    if (mode == 1) {
        __shared__ float red[64];
        if (threadIdx.x < 64) red[threadIdx.x] = 0.0f;
        __syncthreads();
        atomicAdd(&red[2 * lane + 0], acc0t);
        atomicAdd(&red[2 * lane + 1], acc1t);
        __syncthreads();
        if (threadIdx.x < 64)
            atomicAdd(&hsout[threadIdx.x], red[threadIdx.x] * (1.0f / (float)N_NODES));
    }
}

// ---------------- persistent full-sequence LSTM (f32x2) ----------------------
// One kernel does all 24 timesteps; per-node recurrence is independent across
// nodes, so each warp owns 8 nodes, keeps c in regs, h in smem, weights in smem.
#define LSTM_WARPS   12
#define LSTM_THREADS 384
#define LSTM_SMEM_BYTES ((16384 + 128) * 8 + LSTM_WARPS * 1024 * 4)  // 181248

__global__ void __launch_bounds__(LSTM_THREADS, 1) k_lstm_all(
    const float* __restrict__ h_all, float* __restrict__ out_ht) {
    extern __shared__ ull sm[];
    ull* sWi = sm;                 // [64][128]
    ull* sWh = sm + 8192;          // [64][128]
    ull* sB  = sm + 16384;         // [128]
    float* sStage = (float*)(sm + 16512);

    int tid = threadIdx.x, w = tid >> 5, lane = tid & 31;
    for (int i = tid; i < 8192; i += LSTM_THREADS) {
        sWi[i] = g_Wi2[i];
        sWh[i] = g_Wh2[i];
    }
    if (tid < 128) sB[tid] = g_b2[tid];
    __syncthreads();

    float* myX = sStage + w * 1024;
    float* myH = myX + 512;
    const int NGROUPS = (N_NODES + 7) / 8;   // 6250
    const float inv = 1.0f / (float)T_STEPS;

    for (;;) {
        int grp = 0;
        if (lane == 0) grp = atomicAdd(&g_wq, 1);
        grp = __shfl_sync(0xffffffffu, grp, 0);
        if (grp >= NGROUPS) break;
        int n0 = grp * 8;

        ull c2[8];
        float hs0[8], hs1[8];
#pragma unroll
        for (int i = 0; i < 8; i++) { c2[i] = 0ull; hs0[i] = 0.0f; hs1[i] = 0.0f; }
        for (int j = lane; j < 512; j += 32) myH[j] = 0.0f;
        __syncwarp();

        for (int t = 0; t < T_STEPS; t++) {
            // stage x for 8 nodes
#pragma unroll
            for (int j = lane; j < 128; j += 32) {
                int i = j >> 4, q = j & 15;
                int n = n0 + i;
                float4 v = make_float4(0, 0, 0, 0);
                if (n < N_NODES)
                    v = *(const float4*)&h_all[(n * T_STEPS + t) * 64 + q * 4];
                *(float4*)&myX[i * 64 + q * 4] = v;
            }
            __syncwarp();

            ull b0 = sB[lane], b1 = sB[32 + lane], b2v = sB[64 + lane], b3 = sB[96 + lane];
            ull acc[8][4];
#pragma unroll
            for (int i = 0; i < 8; i++) {
                acc[i][0] = b0; acc[i][1] = b1; acc[i][2] = b2v; acc[i][3] = b3;
            }

#pragma unroll 4
            for (int k = 0; k < 64; k++) {
                ull wi0 = sWi[k * 128 + lane];
                ull wi1 = sWi[k * 128 + 32 + lane];
                ull wi2v = sWi[k * 128 + 64 + lane];
                ull wi3 = sWi[k * 128 + 96 + lane];
                ull wh0 = sWh[k * 128 + lane];
                ull wh1 = sWh[k * 128 + 32 + lane];
                ull wh2v = sWh[k * 128 + 64 + lane];
                ull wh3 = sWh[k * 128 + 96 + lane];
#pragma unroll
                for (int i = 0; i < 8; i++) {
                    ull x2 = dup2f(myX[i * 64 + k]);
                    ull h2 = dup2f(myH[i * 64 + k]);
                    acc[i][0] = ffma2(x2, wi0, acc[i][0]);
                    acc[i][1] = ffma2(x2, wi1, acc[i][1]);
                    acc[i][2] = ffma2(x2, wi2v, acc[i][2]);
                    acc[i][3] = ffma2(x2, wi3, acc[i][3]);
                    acc[i][0] = ffma2(h2, wh0, acc[i][0]);
                    acc[i][1] = ffma2(h2, wh1, acc[i][1]);
                    acc[i][2] = ffma2(h2, wh2v, acc[i][2]);
                    acc[i][3] = ffma2(h2, wh3, acc[i][3]);
                }
            }
            __syncwarp();

#pragma unroll
            for (int i = 0; i < 8; i++) {
                float2 gi = unpack2(acc[i][0]);
                float2 gf = unpack2(acc[i][1]);
                float2 gg = unpack2(acc[i][2]);
                float2 go = unpack2(acc[i][3]);
                float2 cp = unpack2(c2[i]);
                float c0 = sig_f(gf.x) * cp.x + sig_f(gi.x) * tanhf(gg.x);
                float c1 = sig_f(gf.y) * cp.y + sig_f(gi.y) * tanhf(gg.y);
                float h0 = sig_f(go.x) * tanhf(c0);
                float h1 = sig_f(go.y) * tanhf(c1);
                c2[i] = pack2f(c0, c1);
                hs0[i] += h0; hs1[i] += h1;
                myH[i * 64 + lane]      = h0;
                myH[i * 64 + lane + 32] = h1;
            }
            __syncwarp();
        }

#pragma unroll
        for (int i = 0; i < 8; i++) {
            int n = n0 + i;
            if (n < N_NODES) {
                out_ht[n * 64 + lane]      = hs0[i] * inv;
                out_ht[n * 64 + lane + 32] = hs1[i] * inv;
            }
        }
    }
}

__global__ void k_join_anchor() {}

// ---------------- launch ----------------------------------------------------
extern "C" void kernel_launch(void* const* d_in, const int* in_sizes, int n_in,
                              void* d_out, int out_size) {
    const float* h     = (const float*)d_in[0];
    const int*   src   = (const int*)d_in[1];
    const int*   dst   = (const int*)d_in[2];
    const float* gamma = (const float*)d_in[3];
    const float* beta  = (const float*)d_in[4];
    const float* W0    = (const float*)d_in[5];
    const float* b0    = (const float*)d_in[6];
    const float* W1    = (const float*)d_in[7];
    const float* b1    = (const float*)d_in[8];
    const float* Wih   = (const float*)d_in[9];
    const float* Whh   = (const float*)d_in[10];
    const float* bih   = (const float*)d_in[11];
    const float* bhh   = (const float*)d_in[12];
    float* out = (float*)d_out;
    (void)in_sizes; (void)n_in;

    cudaFuncSetAttribute(k_lstm_all, cudaFuncAttributeMaxDynamicSharedMemorySize,
                         LSTM_SMEM_BYTES);

    float *pW0s, *pbvec0, *pzero, *pbufM, *pbufY;
    cudaGetSymbolAddress((void**)&pW0s,   g_W0s);
    cudaGetSymbolAddress((void**)&pbvec0, g_bvec0);
    cudaGetSymbolAddress((void**)&pzero,  g_zero64);
    cudaGetSymbolAddress((void**)&pbufM,  g_bufM);
    cudaGetSymbolAddress((void**)&pbufY,  g_bufY);

    // ---- try two-stream fork/join (fallback: everything on stream 0) ----
    cudaStream_t s1 = 0;
    cudaEvent_t eFork = 0, ePrep = 0, eJoin = 0;
    bool multi = (cudaStreamCreateWithFlags(&s1, cudaStreamNonBlocking) == cudaSuccess);
    if (multi) multi = (cudaEventCreateWithFlags(&eFork, cudaEventDisableTiming) == cudaSuccess);
    if (multi) multi = (cudaEventCreateWithFlags(&ePrep, cudaEventDisableTiming) == cudaSuccess);
    if (multi) multi = (cudaEventCreateWithFlags(&eJoin, cudaEventDisableTiming) == cudaSuccess);

    // stream 0: init + BN + weight packing
    k_init<<<512, 256>>>(out, out_size);

    if (multi) multi = (cudaEventRecord(eFork, 0) == cudaSuccess);
    if (multi) multi = (cudaStreamWaitEvent(s1, eFork, 0) == cudaSuccess);
    cudaStream_t sg = multi ? s1 : (cudaStream_t)0;

    k_bnstats<<<1184, 256>>>((const float4*)h);
    k_prep1<<<1, 256>>>(gamma, beta, W0);
    k_prep2<<<32, 256>>>(Wih, Whh);
    k_prep3<<<1, 256>>>(Wih, bih, bhh);

    // graph structure on sg (runs concurrently with BN/prep when multi)
    k_deg<<<800, 256, 0, sg>>>(src, dst);
    k_norm<<<128, 256, 0, sg>>>();
    k_scan<<<1, 1024, 0, sg>>>();
    k_csr<<<800, 256, 0, sg>>>(src, dst);

    if (multi) {
        cudaEventRecord(ePrep, 0);
        cudaStreamWaitEvent(sg, ePrep, 0);   // spatial needs folded W0/bvec0
    }

    // spatial branch on sg
    const int gemm_blocks = (N_NODES + 63) / 64;
    for (int t = 0; t < T_STEPS; t++) {
        k_gemm64<<<gemm_blocks, 256, 0, sg>>>(h + t * 64, T_STEPS * 64, pW0s, pbvec0, pbufM);
        k_gather<<<640, 256, 0, sg>>>(pbufM, b0, pbufY, nullptr, 0);
        k_gemm64<<<gemm_blocks, 256, 0, sg>>>(pbufY, 64, W1, pzero, pbufM);
        k_gather<<<296, 256, 0, sg>>>(pbufM, b1, nullptr, out + t * 64, 1);
    }
    if (multi) cudaEventRecord(eJoin, sg);

    // temporal branch on stream 0 (overlaps spatial when multi)
    k_lstm_all<<<148, LSTM_THREADS, LSTM_SMEM_BYTES, 0>>>(h, out + T_STEPS * 64);

    if (multi) {
        cudaStreamWaitEvent(0, eJoin, 0);
        k_join_anchor<<<1, 1, 0, 0>>>();
    }
    // note: s1/events intentionally not destroyed (kernel_launch is called
    // only for correctness + capture; destroying mid-capture is unsafe)
}

// round 3
// speedup vs baseline: 1.6416x; 1.0629x over previous
#include <cuda_runtime.h>
#include <cuda_bf16.h>
#include <math.h>

#define N_NODES 50000
#define T_STEPS 24
#define E_EDGES 800000
#define NT_ROWS (N_NODES * T_STEPS)

typedef unsigned long long ull;

// ---------------- f32x2 / bf16 packed helpers -------------------------------
__device__ __forceinline__ ull ffma2(ull a, ull b, ull c) {
    ull d;
    asm("fma.rn.f32x2 %0, %1, %2, %3;" : "=l"(d) : "l"(a), "l"(b), "l"(c));
    return d;
}
__device__ __forceinline__ ull dup2f(float x) {
    ull r;
    asm("mov.b64 %0, {%1, %1};" : "=l"(r) : "f"(x));
    return r;
}
__device__ __forceinline__ ull pack2f(float x, float y) {
    ull r;
    asm("mov.b64 %0, {%1, %2};" : "=l"(r) : "f"(x), "f"(y));
    return r;
}
__device__ __forceinline__ float2 unpack2(ull v) {
    float2 r;
    asm("mov.b64 {%0, %1}, %2;" : "=f"(r.x), "=f"(r.y) : "l"(v));
    return r;
}
__device__ __forceinline__ unsigned bf2pack(float x, float y) {
    __nv_bfloat162 b = __float22bfloat162_rn(make_float2(x, y));
    return *(unsigned*)&b;
}
__device__ __forceinline__ float2 bf2unpack(unsigned u) {
    __nv_bfloat162 b = *(__nv_bfloat162*)&u;
    return __bfloat1622float2(b);
}

// ---------------- scratch (device globals; no runtime allocation) ----------
__device__ float g_sum[64];
__device__ float g_sumsq[64];
__device__ float g_a[64];
__device__ float g_bsh[64];
__device__ float g_W0s[64 * 64];
__device__ float g_bvec0[64];
__device__ ull   g_Wi2[64 * 128];       // packed (a*Wih) pairs: [k][j*32+l]
__device__ ull   g_Wh2[64 * 128];       // packed Whh pairs
__device__ ull   g_b2[128];             // packed gate bias pairs
__device__ float g_outnorm[N_NODES];
__device__ float g_innorm[N_NODES];
__device__ int   g_degout[N_NODES];
__device__ int   g_degin[N_NODES];
__device__ int   g_rowptr[N_NODES + 1];
__device__ int   g_cursor[N_NODES];
__device__ int   g_csrsrc[E_EDGES];
__device__ unsigned g_M1[T_STEPS * N_NODES * 32];   // bf16x2 messages layer 1
__device__ unsigned g_M2[T_STEPS * N_NODES * 32];   // bf16x2 messages layer 2
__device__ int   g_wq;

__device__ __forceinline__ float gelu_f(float x) {
    return 0.5f * x * (1.0f + erff(x * 0.70710678118654752440f));
}
__device__ __forceinline__ float sig_f(float x) {
    return 1.0f / (1.0f + expf(-x));
}

// ---------------- init: zero output + accumulators -------------------------
__global__ void k_init(float* out, int out_n) {
    int i = blockIdx.x * blockDim.x + threadIdx.x;
    int stride = gridDim.x * blockDim.x;
    for (int j = i; j < out_n; j += stride) out[j] = 0.0f;
    for (int j = i; j < N_NODES; j += stride) { g_degout[j] = 0; g_degin[j] = 0; }
    if (i < 64) { g_sum[i] = 0.0f; g_sumsq[i] = 0.0f; }
    if (i == 0) g_wq = 0;
}

// ---------------- BN stats ---------------------------------------------------
__global__ void k_bnstats(const float4* __restrict__ h4) {
    __shared__ float ss[64], sq[64];
    int tid = threadIdx.x;
    if (tid < 64) { ss[tid] = 0.0f; sq[tid] = 0.0f; }
    __syncthreads();
    const int total4 = NT_ROWS * 16;
    float4 s = make_float4(0, 0, 0, 0);
    float4 q = make_float4(0, 0, 0, 0);
    for (int i = blockIdx.x * blockDim.x + tid; i < total4; i += gridDim.x * blockDim.x) {
        float4 v = h4[i];
        s.x += v.x; s.y += v.y; s.z += v.z; s.w += v.w;
        q.x += v.x * v.x; q.y += v.y * v.y; q.z += v.z * v.z; q.w += v.w * v.w;
    }
    int c = (tid & 15) * 4;
    atomicAdd(&ss[c + 0], s.x); atomicAdd(&ss[c + 1], s.y);
    atomicAdd(&ss[c + 2], s.z); atomicAdd(&ss[c + 3], s.w);
    atomicAdd(&sq[c + 0], q.x); atomicAdd(&sq[c + 1], q.y);
    atomicAdd(&sq[c + 2], q.z); atomicAdd(&sq[c + 3], q.w);
    __syncthreads();
    if (tid < 64) {
        atomicAdd(&g_sum[tid], ss[tid]);
        atomicAdd(&g_sumsq[tid], sq[tid]);
    }
}

// ---------------- BN finalize + fold into W0 --------------------------------
__global__ void k_prep1(const float* __restrict__ gamma, const float* __restrict__ beta,
                        const float* __restrict__ W0) {
    __shared__ float sa[64], sb[64];
    int tid = threadIdx.x;  // 256 threads
    if (tid < 64) {
        float mu  = g_sum[tid]   * (1.0f / (float)NT_ROWS);
        float var = g_sumsq[tid] * (1.0f / (float)NT_ROWS) - mu * mu;
        float a = gamma[tid] * rsqrtf(var + 1e-5f);
        sa[tid] = a;
        sb[tid] = beta[tid] - mu * a;
        g_a[tid] = a; g_bsh[tid] = sb[tid];
    }
    __syncthreads();
    for (int idx = tid; idx < 4096; idx += 256) {
        int k = idx >> 6;
        g_W0s[idx] = sa[k] * W0[idx];
    }
    if (tid < 64) {
        float acc = 0.0f;
        for (int k = 0; k < 64; k++) acc += sb[k] * W0[k * 64 + tid];
        g_bvec0[tid] = acc;
    }
}

// ---------------- pack LSTM weights as f32x2 pairs ---------------------------
__global__ void k_prep2(const float* __restrict__ Wih, const float* __restrict__ Whh) {
    int idx = blockIdx.x * blockDim.x + threadIdx.x;   // 0..8191
    if (idx >= 8192) return;
    int k = idx >> 7, r = idx & 127;
    int j = r >> 5, l = r & 31;
    int gA = j * 64 + l, gB = gA + 32;
    float a = g_a[k];
    g_Wi2[idx] = pack2f(a * Wih[gA * 64 + k], a * Wih[gB * 64 + k]);
    g_Wh2[idx] = pack2f(Whh[gA * 64 + k], Whh[gB * 64 + k]);
}

__global__ void k_prep3(const float* __restrict__ Wih,
                        const float* __restrict__ bih, const float* __restrict__ bhh) {
    __shared__ float sgb[256];
    int g = threadIdx.x;  // 256 threads
    float acc = bih[g] + bhh[g];
    for (int k = 0; k < 64; k++) acc += g_bsh[k] * Wih[g * 64 + k];
    sgb[g] = acc;
    __syncthreads();
    if (g < 128) {
        int j = g >> 5, l = g & 31;
        g_b2[g] = pack2f(sgb[j * 64 + l], sgb[j * 64 + 32 + l]);
    }
}

// ---------------- degrees / norms / CSR -------------------------------------
__global__ void k_deg(const int* __restrict__ src, const int* __restrict__ dst) {
    for (int e = blockIdx.x * blockDim.x + threadIdx.x; e < E_EDGES;
         e += gridDim.x * blockDim.x) {
        atomicAdd(&g_degout[src[e]], 1);
        atomicAdd(&g_degin[dst[e]], 1);
    }
}

__global__ void k_norm() {
    for (int n = blockIdx.x * blockDim.x + threadIdx.x; n < N_NODES;
         n += gridDim.x * blockDim.x) {
        g_outnorm[n] = rsqrtf(fmaxf((float)g_degout[n], 1.0f));
        g_innorm[n]  = rsqrtf(fmaxf((float)g_degin[n], 1.0f));
    }
}

__global__ void k_scan() {
    __shared__ int s[1024];
    const int CH = 49;
    int tid = threadIdx.x;
    int base = tid * CH;
    int tot = 0;
    for (int i = 0; i < CH; i++) {
        int idx = base + i;
        if (idx < N_NODES) tot += g_degin[idx];
    }
    s[tid] = tot;
    __syncthreads();
    for (int off = 1; off < 1024; off <<= 1) {
        int v = (tid >= off) ? s[tid - off] : 0;
        __syncthreads();
        s[tid] += v;
        __syncthreads();
    }
    int run = (tid > 0) ? s[tid - 1] : 0;
    for (int i = 0; i < CH; i++) {
        int idx = base + i;
        if (idx < N_NODES) {
            g_rowptr[idx] = run;
            g_cursor[idx] = run;
            run += g_degin[idx];
        } else if (idx == N_NODES) {
            g_rowptr[idx] = run;
        }
    }
}

__global__ void k_csr(const int* __restrict__ src, const int* __restrict__ dst) {
    for (int e = blockIdx.x * blockDim.x + threadIdx.x; e < E_EDGES;
         e += gridDim.x * blockDim.x) {
        int pos = atomicAdd(&g_cursor[dst[e]], 1);
        g_csrsrc[pos] = src[e];
    }
}

// ---------------- batched layer-1 GEMM over all t ----------------------------
// m1[t][n] = outnorm[n] * (h[n,t,:] @ W0s + bvec0), output bf16x2
__global__ void __launch_bounds__(256) k_gemm_b(const float* __restrict__ X) {
    __shared__ __align__(16) float xs[64][64];
    __shared__ __align__(16) ull wsp[64][32];
    __shared__ float sbias[64];
    int tid = threadIdx.x;
    int t = blockIdx.y;
    int n0 = blockIdx.x * 64;

    for (int idx = tid; idx < 2048; idx += 256) {
        int k = idx >> 5, c = idx & 31;
        float2 w = *(const float2*)&g_W0s[k * 64 + c * 2];
        wsp[k][c] = pack2f(w.x, w.y);
    }
    if (tid < 64) sbias[tid] = g_bvec0[tid];
    for (int idx = tid; idx < 1024; idx += 256) {
        int r = idx >> 4, q = idx & 15;
        int n = n0 + r;
        if (n < N_NODES)
            *(float4*)&xs[r][q * 4] =
                *(const float4*)&X[(n * T_STEPS + t) * 64 + q * 4];
    }
    __syncthreads();

    int r0 = (tid >> 4) * 4;
    int cg = (tid & 15);          // col group: cols cg*4 .. cg*4+3
    ull acc[4][2] = {};
#pragma unroll 8
    for (int k = 0; k < 64; k++) {
        ulonglong2 wp = *(ulonglong2*)&wsp[k][cg * 2];
#pragma unroll
        for (int i = 0; i < 4; i++) {
            ull x2 = dup2f(xs[r0 + i][k]);
            acc[i][0] = ffma2(x2, wp.x, acc[i][0]);
            acc[i][1] = ffma2(x2, wp.y, acc[i][1]);
        }
    }
    int c0 = cg * 4;
#pragma unroll
    for (int i = 0; i < 4; i++) {
        int n = n0 + r0 + i;
        if (n < N_NODES) {
            float sc = g_outnorm[n];
            float2 p0 = unpack2(acc[i][0]);
            float2 p1 = unpack2(acc[i][1]);
            uint2 o;
            o.x = bf2pack(sc * (p0.x + sbias[c0 + 0]), sc * (p0.y + sbias[c0 + 1]));
            o.y = bf2pack(sc * (p1.x + sbias[c0 + 2]), sc * (p1.y + sbias[c0 + 3]));
            *(uint2*)&g_M1[(t * N_NODES + n) * 32 + (c0 >> 1)] = o;
        }
    }
}

// ---------------- gather layer1 + gelu + fused y@W1 -> m2 (bf16) ------------
__global__ void __launch_bounds__(256) k_gatherA(const float* __restrict__ W1,
                                                 const float* __restrict__ b0) {
    __shared__ __align__(16) ull sW1p[64 * 32];
    __shared__ float sY[8][64];
    int tid = threadIdx.x;
    int t = blockIdx.y;
    int lane = tid & 31, w = tid >> 5;
    for (int idx = tid; idx < 2048; idx += 256) {
        int k = idx >> 5, c = idx & 31;
        float2 ww = *(const float2*)&W1[k * 64 + c * 2];
        sW1p[idx] = pack2f(ww.x, ww.y);
    }
    __syncthreads();

    int warpg = blockIdx.x * 8 + w;
    int nwarps = gridDim.x * 8;
    float bb0 = b0[2 * lane], bb1 = b0[2 * lane + 1];
    unsigned base = (unsigned)t * N_NODES;

    for (int v = warpg; v < N_NODES; v += nwarps) {
        int s = g_rowptr[v], e = g_rowptr[v + 1];
        float a0 = 0.0f, a1 = 0.0f;
        int i = s;
        for (; i + 4 <= e; i += 4) {
            int u0 = g_csrsrc[i + 0];
            int u1 = g_csrsrc[i + 1];
            int u2 = g_csrsrc[i + 2];
            int u3 = g_csrsrc[i + 3];
            float2 m0 = bf2unpack(g_M1[(base + u0) * 32 + lane]);
            float2 m1 = bf2unpack(g_M1[(base + u1) * 32 + lane]);
            float2 m2 = bf2unpack(g_M1[(base + u2) * 32 + lane]);
            float2 m3 = bf2unpack(g_M1[(base + u3) * 32 + lane]);
            a0 += (m0.x + m1.x) + (m2.x + m3.x);
            a1 += (m0.y + m1.y) + (m2.y + m3.y);
        }
        for (; i < e; i++) {
            int u = g_csrsrc[i];
            float2 m = bf2unpack(g_M1[(base + u) * 32 + lane]);
            a0 += m.x; a1 += m.y;
        }
        float inn = g_innorm[v];
        sY[w][2 * lane]     = gelu_f(a0 * inn + bb0);
        sY[w][2 * lane + 1] = gelu_f(a1 * inn + bb1);
        __syncwarp();
        ull acc = 0ull;
#pragma unroll 8
        for (int k = 0; k < 64; k++)
            acc = ffma2(dup2f(sY[w][k]), sW1p[k * 32 + lane], acc);
        float2 p = unpack2(acc);
        float sc = g_outnorm[v];
        g_M2[(base + v) * 32 + lane] = bf2pack(sc * p.x, sc * p.y);
        __syncwarp();
    }
}

// ---------------- gather layer2 + gelu + mean -> hs --------------------------
__global__ void __launch_bounds__(256) k_gatherB(const float* __restrict__ b1,
                                                 float* __restrict__ out) {
    int tid = threadIdx.x;
    int t = blockIdx.y;
    int lane = tid & 31;
    int warpg = blockIdx.x * 8 + (tid >> 5);
    int nwarps = gridDim.x * 8;
    float bb0 = b1[2 * lane], bb1 = b1[2 * lane + 1];
    unsigned base = (unsigned)t * N_NODES;
    float acc0t = 0.0f, acc1t = 0.0f;

    for (int v = warpg; v < N_NODES; v += nwarps) {
        int s = g_rowptr[v], e = g_rowptr[v + 1];
        float a0 = 0.0f, a1 = 0.0f;
        int i = s;
        for (; i + 4 <= e; i += 4) {
            int u0 = g_csrsrc[i + 0];
            int u1 = g_csrsrc[i + 1];
            int u2 = g_csrsrc[i + 2];
            int u3 = g_csrsrc[i + 3];
            float2 m0 = bf2unpack(g_M2[(base + u0) * 32 + lane]);
            float2 m1 = bf2unpack(g_M2[(base + u1) * 32 + lane]);
            float2 m2 = bf2unpack(g_M2[(base + u2) * 32 + lane]);
            float2 m3 = bf2unpack(g_M2[(base + u3) * 32 + lane]);
            a0 += (m0.x + m1.x) + (m2.x + m3.x);
            a1 += (m0.y + m1.y) + (m2.y + m3.y);
        }
        for (; i < e; i++) {
            int u = g_csrsrc[i];
            float2 m = bf2unpack(g_M2[(base + u) * 32 + lane]);
            a0 += m.x; a1 += m.y;
        }
        float inn = g_innorm[v];
        acc0t += gelu_f(a0 * inn + bb0);
        acc1t += gelu_f(a1 * inn + bb1);
    }
    __shared__ float red[64];
    if (tid < 64) red[tid] = 0.0f;
    __syncthreads();
    atomicAdd(&red[2 * lane + 0], acc0t);
    atomicAdd(&red[2 * lane + 1], acc1t);
    __syncthreads();
    if (tid < 64)
        atomicAdd(&out[t * 64 + tid], red[tid] * (1.0f / (float)N_NODES));
}

// ---------------- persistent full-sequence LSTM (f32x2) ----------------------
// 8 warps/block (small footprint so spatial kernels co-reside on the same SM).
#define LSTM_WARPS   8
#define LSTM_THREADS 256
#define LSTM_SMEM_BYTES ((8192 + 8192 + 128) * 8 + LSTM_WARPS * 1024 * 4)

__global__ void __launch_bounds__(LSTM_THREADS, 1) k_lstm_all(
    const float* __restrict__ h_all, float* __restrict__ out_ht) {
    extern __shared__ ull sm[];
    ull* sWi = sm;                 // [64][128]
    ull* sWh = sm + 8192;          // [64][128]
    ull* sB  = sm + 16384;         // [128]
    float* sStage = (float*)(sm + 16512);

    int tid = threadIdx.x, w = tid >> 5, lane = tid & 31;
    for (int i = tid; i < 8192; i += LSTM_THREADS) {
        sWi[i] = g_Wi2[i];
        sWh[i] = g_Wh2[i];
    }
    if (tid < 128) sB[tid] = g_b2[tid];
    __syncthreads();

    float* myX = sStage + w * 1024;
    float* myH = myX + 512;
    const int NGROUPS = (N_NODES + 7) / 8;   // 6250
    const float inv = 1.0f / (float)T_STEPS;

    for (;;) {
        int grp = 0;
        if (lane == 0) grp = atomicAdd(&g_wq, 1);
        grp = __shfl_sync(0xffffffffu, grp, 0);
        if (grp >= NGROUPS) break;
        int n0 = grp * 8;

        ull c2[8];
        float hs0[8], hs1[8];
#pragma unroll
        for (int i = 0; i < 8; i++) { c2[i] = 0ull; hs0[i] = 0.0f; hs1[i] = 0.0f; }
        for (int j = lane; j < 512; j += 32) myH[j] = 0.0f;
        __syncwarp();

        for (int t = 0; t < T_STEPS; t++) {
#pragma unroll
            for (int j = lane; j < 128; j += 32) {
                int i = j >> 4, q = j & 15;
                int n = n0 + i;
                float4 v = make_float4(0, 0, 0, 0);
                if (n < N_NODES)
                    v = *(const float4*)&h_all[(n * T_STEPS + t) * 64 + q * 4];
                *(float4*)&myX[i * 64 + q * 4] = v;
            }
            __syncwarp();

            ull b0 = sB[lane], b1 = sB[32 + lane], b2v = sB[64 + lane], b3 = sB[96 + lane];
            ull acc[8][4];
#pragma unroll
            for (int i = 0; i < 8; i++) {
                acc[i][0] = b0; acc[i][1] = b1; acc[i][2] = b2v; acc[i][3] = b3;
            }

#pragma unroll 4
            for (int k = 0; k < 64; k++) {
                ull wi0 = sWi[k * 128 + lane];
                ull wi1 = sWi[k * 128 + 32 + lane];
                ull wi2v = sWi[k * 128 + 64 + lane];
                ull wi3 = sWi[k * 128 + 96 + lane];
                ull wh0 = sWh[k * 128 + lane];
                ull wh1 = sWh[k * 128 + 32 + lane];
                ull wh2v = sWh[k * 128 + 64 + lane];
                ull wh3 = sWh[k * 128 + 96 + lane];
#pragma unroll
                for (int i = 0; i < 8; i++) {
                    ull x2 = dup2f(myX[i * 64 + k]);
                    ull h2 = dup2f(myH[i * 64 + k]);
                    acc[i][0] = ffma2(x2, wi0, acc[i][0]);
                    acc[i][1] = ffma2(x2, wi1, acc[i][1]);
                    acc[i][2] = ffma2(x2, wi2v, acc[i][2]);
                    acc[i][3] = ffma2(x2, wi3, acc[i][3]);
                    acc[i][0] = ffma2(h2, wh0, acc[i][0]);
                    acc[i][1] = ffma2(h2, wh1, acc[i][1]);
                    acc[i][2] = ffma2(h2, wh2v, acc[i][2]);
                    acc[i][3] = ffma2(h2, wh3, acc[i][3]);
                }
            }
            __syncwarp();

#pragma unroll
            for (int i = 0; i < 8; i++) {
                float2 gi = unpack2(acc[i][0]);
                float2 gf = unpack2(acc[i][1]);
                float2 gg = unpack2(acc[i][2]);
                float2 go = unpack2(acc[i][3]);
                float2 cp = unpack2(c2[i]);
                float c0 = sig_f(gf.x) * cp.x + sig_f(gi.x) * tanhf(gg.x);
                float c1 = sig_f(gf.y) * cp.y + sig_f(gi.y) * tanhf(gg.y);
                float h0 = sig_f(go.x) * tanhf(c0);
                float h1 = sig_f(go.y) * tanhf(c1);
                c2[i] = pack2f(c0, c1);
                hs0[i] += h0; hs1[i] += h1;
                myH[i * 64 + lane]      = h0;
                myH[i * 64 + lane + 32] = h1;
            }
            __syncwarp();
        }

#pragma unroll
        for (int i = 0; i < 8; i++) {
            int n = n0 + i;
            if (n < N_NODES) {
                out_ht[n * 64 + lane]      = hs0[i] * inv;
                out_ht[n * 64 + lane + 32] = hs1[i] * inv;
            }
        }
    }
}

__global__ void k_join_anchor() {}

// ---------------- launch ----------------------------------------------------
extern "C" void kernel_launch(void* const* d_in, const int* in_sizes, int n_in,
                              void* d_out, int out_size) {
    const float* h     = (const float*)d_in[0];
    const int*   src   = (const int*)d_in[1];
    const int*   dst   = (const int*)d_in[2];
    const float* gamma = (const float*)d_in[3];
    const float* beta  = (const float*)d_in[4];
    const float* W0    = (const float*)d_in[5];
    const float* b0    = (const float*)d_in[6];
    const float* W1    = (const float*)d_in[7];
    const float* b1    = (const float*)d_in[8];
    const float* Wih   = (const float*)d_in[9];
    const float* Whh   = (const float*)d_in[10];
    const float* bih   = (const float*)d_in[11];
    const float* bhh   = (const float*)d_in[12];
    float* out = (float*)d_out;
    (void)in_sizes; (void)n_in; (void)W0;

    cudaFuncSetAttribute(k_lstm_all, cudaFuncAttributeMaxDynamicSharedMemorySize,
                         LSTM_SMEM_BYTES);

    // ---- two-stream fork/join (fallback: everything on stream 0) ----
    cudaStream_t s1 = 0;
    cudaEvent_t eFork = 0, ePrep = 0, eJoin = 0;
    bool multi = (cudaStreamCreateWithFlags(&s1, cudaStreamNonBlocking) == cudaSuccess);
    if (multi) multi = (cudaEventCreateWithFlags(&eFork, cudaEventDisableTiming) == cudaSuccess);
    if (multi) multi = (cudaEventCreateWithFlags(&ePrep, cudaEventDisableTiming) == cudaSuccess);
    if (multi) multi = (cudaEventCreateWithFlags(&eJoin, cudaEventDisableTiming) == cudaSuccess);

    k_init<<<512, 256>>>(out, out_size);

    if (multi) multi = (cudaEventRecord(eFork, 0) == cudaSuccess);
    if (multi) multi = (cudaStreamWaitEvent(s1, eFork, 0) == cudaSuccess);
    cudaStream_t sg = multi ? s1 : (cudaStream_t)0;

    // stream 0: BN stats + weight folding/packing, then persistent LSTM
    k_bnstats<<<1184, 256>>>((const float4*)h);
    k_prep1<<<1, 256>>>(gamma, beta, d_in[5] ? (const float*)d_in[5] : gamma);
    k_prep2<<<32, 256>>>(Wih, Whh);
    k_prep3<<<1, 256>>>(Wih, bih, bhh);
    if (multi) cudaEventRecord(ePrep, 0);
    k_lstm_all<<<148, LSTM_THREADS, LSTM_SMEM_BYTES, 0>>>(h, out + T_STEPS * 64);

    // sg: graph structure, then batched spatial stages
    k_deg<<<800, 256, 0, sg>>>(src, dst);
    k_norm<<<128, 256, 0, sg>>>();
    k_scan<<<1, 1024, 0, sg>>>();
    k_csr<<<800, 256, 0, sg>>>(src, dst);
    if (multi) cudaStreamWaitEvent(sg, ePrep, 0);   // spatial needs folded W0/bvec0

    dim3 ggemm((N_NODES + 63) / 64, T_STEPS);
    dim3 gA(104, T_STEPS);
    dim3 gB(52, T_STEPS);
    k_gemm_b<<<ggemm, 256, 0, sg>>>(h);
    k_gatherA<<<gA, 256, 0, sg>>>(W1, b0);
    k_gatherB<<<gB, 256, 0, sg>>>(b1, out);

    if (multi) {
        cudaEventRecord(eJoin, sg);
        cudaStreamWaitEvent(0, eJoin, 0);
        k_join_anchor<<<1, 1, 0, 0>>>();
    }
}

// round 5
// speedup vs baseline: 1.8096x; 1.1024x over previous
#include <cuda_runtime.h>
#include <cuda_bf16.h>
#include <math.h>
#include <stdint.h>

#define N_NODES 50000
#define T_STEPS 24
#define E_EDGES 800000
#define NT_ROWS (N_NODES * T_STEPS)
#define GX_CHUNKS (NT_ROWS / 64)        // 18750 exact

typedef unsigned long long ull;

// ---------------- f32x2 / bf16 packed helpers -------------------------------
__device__ __forceinline__ ull ffma2(ull a, ull b, ull c) {
    ull d;
    asm("fma.rn.f32x2 %0, %1, %2, %3;" : "=l"(d) : "l"(a), "l"(b), "l"(c));
    return d;
}
__device__ __forceinline__ ull dup2f(float x) {
    ull r; asm("mov.b64 %0, {%1, %1};" : "=l"(r) : "f"(x)); return r;
}
__device__ __forceinline__ ull pack2f(float x, float y) {
    ull r; asm("mov.b64 %0, {%1, %2};" : "=l"(r) : "f"(x), "f"(y)); return r;
}
__device__ __forceinline__ float2 unpack2(ull v) {
    float2 r; asm("mov.b64 {%0, %1}, %2;" : "=f"(r.x), "=f"(r.y) : "l"(v)); return r;
}
__device__ __forceinline__ unsigned bf2pack(float x, float y) {
    __nv_bfloat162 b = __float22bfloat162_rn(make_float2(x, y));
    return *(unsigned*)&b;
}
__device__ __forceinline__ float2 bf2unpack(unsigned u) {
    __nv_bfloat162 b = *(__nv_bfloat162*)&u;
    return __bfloat1622float2(b);
}
__device__ __forceinline__ unsigned tf32r(float f) {
    unsigned u; asm("cvt.rna.tf32.f32 %0, %1;" : "=r"(u) : "f"(f)); return u;
}

// ---------------- scratch (device globals) ----------------------------------
__device__ float g_sum[64];
__device__ float g_sumsq[64];
__device__ float g_a[64];
__device__ float g_bsh[64];
__device__ float g_W0s[64 * 64];
__device__ float g_bvec0[64];
__device__ ull   g_Wh2[64 * 128];
__device__ float g_gbias[256];
__device__ unsigned g_Wg[256 * 64];               // tf32 bits of a*Wih, [g][k]
__device__ float g_outnorm[N_NODES];
__device__ float g_innorm[N_NODES];
__device__ int   g_degout[N_NODES];
__device__ int   g_degin[N_NODES];
__device__ int   g_rowptr[N_NODES + 1];
__device__ int   g_cursor[N_NODES];
__device__ int   g_csrsrc[E_EDGES];
__device__ unsigned g_M1[T_STEPS * N_NODES * 32];
__device__ unsigned g_M2[T_STEPS * N_NODES * 32];
__device__ float g_GX[(size_t)NT_ROWS * 256];     // gate x-projection (+bias)
__device__ int   g_wq;

__device__ __forceinline__ float gelu_f(float x) {
    return 0.5f * x * (1.0f + erff(x * 0.70710678118654752440f));
}
__device__ __forceinline__ float sig_f(float x) {
    return 1.0f / (1.0f + expf(-x));
}

// ---------------- init -------------------------------------------------------
__global__ void k_init(float* out, int out_n) {
    int i = blockIdx.x * blockDim.x + threadIdx.x;
    int stride = gridDim.x * blockDim.x;
    for (int j = i; j < out_n; j += stride) out[j] = 0.0f;
    for (int j = i; j < N_NODES; j += stride) { g_degout[j] = 0; g_degin[j] = 0; }
    if (i < 64) { g_sum[i] = 0.0f; g_sumsq[i] = 0.0f; }
    if (i == 0) g_wq = 0;
}

// ---------------- BN stats ---------------------------------------------------
__global__ void k_bnstats(const float4* __restrict__ h4) {
    __shared__ float ss[64], sq[64];
    int tid = threadIdx.x;
    if (tid < 64) { ss[tid] = 0.0f; sq[tid] = 0.0f; }
    __syncthreads();
    const int total4 = NT_ROWS * 16;
    float4 s = make_float4(0, 0, 0, 0);
    float4 q = make_float4(0, 0, 0, 0);
    for (int i = blockIdx.x * blockDim.x + tid; i < total4; i += gridDim.x * blockDim.x) {
        float4 v = h4[i];
        s.x += v.x; s.y += v.y; s.z += v.z; s.w += v.w;
        q.x += v.x * v.x; q.y += v.y * v.y; q.z += v.z * v.z; q.w += v.w * v.w;
    }
    int c = (tid & 15) * 4;
    atomicAdd(&ss[c + 0], s.x); atomicAdd(&ss[c + 1], s.y);
    atomicAdd(&ss[c + 2], s.z); atomicAdd(&ss[c + 3], s.w);
    atomicAdd(&sq[c + 0], q.x); atomicAdd(&sq[c + 1], q.y);
    atomicAdd(&sq[c + 2], q.z); atomicAdd(&sq[c + 3], q.w);
    __syncthreads();
    if (tid < 64) {
        atomicAdd(&g_sum[tid], ss[tid]);
        atomicAdd(&g_sumsq[tid], sq[tid]);
    }
}

// ---------------- BN finalize + fold into W0 --------------------------------
__global__ void k_prep1(const float* __restrict__ gamma, const float* __restrict__ beta,
                        const float* __restrict__ W0) {
    __shared__ float sa[64], sb[64];
    int tid = threadIdx.x;  // 256
    if (tid < 64) {
        float mu  = g_sum[tid]   * (1.0f / (float)NT_ROWS);
        float var = g_sumsq[tid] * (1.0f / (float)NT_ROWS) - mu * mu;
        float a = gamma[tid] * rsqrtf(var + 1e-5f);
        sa[tid] = a;
        sb[tid] = beta[tid] - mu * a;
        g_a[tid] = a; g_bsh[tid] = sb[tid];
    }
    __syncthreads();
    for (int idx = tid; idx < 4096; idx += 256) {
        int k = idx >> 6;
        g_W0s[idx] = sa[k] * W0[idx];
    }
    if (tid < 64) {
        float acc = 0.0f;
        for (int k = 0; k < 64; k++) acc += sb[k] * W0[k * 64 + tid];
        g_bvec0[tid] = acc;
    }
}

// ---------------- pack Whh pairs ---------------------------------------------
__global__ void k_prep2(const float* __restrict__ Whh) {
    int idx = blockIdx.x * blockDim.x + threadIdx.x;   // 0..8191
    if (idx >= 8192) return;
    int k = idx >> 7, r = idx & 127;
    int j = r >> 5, l = r & 31;
    int gA = j * 64 + l, gB = gA + 32;
    g_Wh2[idx] = pack2f(Whh[gA * 64 + k], Whh[gB * 64 + k]);
}

// ---------------- gate bias (fp32) -------------------------------------------
__global__ void k_prep3(const float* __restrict__ Wih,
                        const float* __restrict__ bih, const float* __restrict__ bhh) {
    int g = threadIdx.x;  // 256
    float acc = bih[g] + bhh[g];
    for (int k = 0; k < 64; k++) acc += g_bsh[k] * Wih[g * 64 + k];
    g_gbias[g] = acc;
}

// ---------------- tf32 weight tile: (a*Wih)[256 x 64] ------------------------
__global__ void k_prepW(const float* __restrict__ Wih) {
    int idx = blockIdx.x * blockDim.x + threadIdx.x;   // 0..16383
    if (idx >= 16384) return;
    int g = idx >> 6, k = idx & 63;
    g_Wg[idx] = tf32r(g_a[k] * Wih[g * 64 + k]);
}

// ---------------- degrees / norms / CSR --------------------------------------
__global__ void k_deg(const int* __restrict__ src, const int* __restrict__ dst) {
    for (int e = blockIdx.x * blockDim.x + threadIdx.x; e < E_EDGES;
         e += gridDim.x * blockDim.x) {
        atomicAdd(&g_degout[src[e]], 1);
        atomicAdd(&g_degin[dst[e]], 1);
    }
}

__global__ void k_norm() {
    for (int n = blockIdx.x * blockDim.x + threadIdx.x; n < N_NODES;
         n += gridDim.x * blockDim.x) {
        g_outnorm[n] = rsqrtf(fmaxf((float)g_degout[n], 1.0f));
        g_innorm[n]  = rsqrtf(fmaxf((float)g_degin[n], 1.0f));
    }
}

__global__ void k_scan() {
    __shared__ int s[1024];
    const int CH = 49;
    int tid = threadIdx.x;
    int base = tid * CH;
    int tot = 0;
    for (int i = 0; i < CH; i++) {
        int idx = base + i;
        if (idx < N_NODES) tot += g_degin[idx];
    }
    s[tid] = tot;
    __syncthreads();
    for (int off = 1; off < 1024; off <<= 1) {
        int v = (tid >= off) ? s[tid - off] : 0;
        __syncthreads();
        s[tid] += v;
        __syncthreads();
    }
    int run = (tid > 0) ? s[tid - 1] : 0;
    for (int i = 0; i < CH; i++) {
        int idx = base + i;
        if (idx < N_NODES) {
            g_rowptr[idx] = run;
            g_cursor[idx] = run;
            run += g_degin[idx];
        } else if (idx == N_NODES) {
            g_rowptr[idx] = run;
        }
    }
}

__global__ void k_csr(const int* __restrict__ src, const int* __restrict__ dst) {
    for (int e = blockIdx.x * blockDim.x + threadIdx.x; e < E_EDGES;
         e += gridDim.x * blockDim.x) {
        int pos = atomicAdd(&g_cursor[dst[e]], 1);
        g_csrsrc[pos] = src[e];
    }
}

// ---------------- GX via mma.sync tf32: 64 rows x 256 gates per chunk --------
// Warp = all 64 rows x 32 cols. B fragments (weights) persist in registers.
__global__ void __launch_bounds__(256, 1) k_gx(const float* __restrict__ h) {
    __shared__ float xs[64][68];      // tf32-rounded A tile, pad 68 (conflict-free)
    __shared__ float sbias[256];
    int tid = threadIdx.x, w = tid >> 5, lane = tid & 31;
    int gid = lane >> 2, tig = lane & 3;
    int cb = w * 32;

    sbias[tid] = g_gbias[tid];

    // load B fragments once: [nt][ks][2]
    unsigned B[4][8][2];
#pragma unroll
    for (int nt = 0; nt < 4; nt++) {
        int col = cb + nt * 8 + gid;
#pragma unroll
        for (int ks = 0; ks < 8; ks++) {
            B[nt][ks][0] = g_Wg[col * 64 + ks * 8 + tig];
            B[nt][ks][1] = g_Wg[col * 64 + ks * 8 + tig + 4];
        }
    }
    __syncthreads();

    for (int chunk = blockIdx.x; chunk < GX_CHUNKS; chunk += gridDim.x) {
        size_t row0 = (size_t)chunk * 64;
        // stage A tile (64 x 64), tf32-rounded
#pragma unroll
        for (int i = 0; i < 4; i++) {
            int idx = tid + i * 256;          // 0..1023 float4s
            int r = idx >> 4, q = idx & 15;
            float4 v = *(const float4*)&h[(row0 + r) * 64 + q * 4];
            float4 u;
            u.x = __uint_as_float(tf32r(v.x));
            u.y = __uint_as_float(tf32r(v.y));
            u.z = __uint_as_float(tf32r(v.z));
            u.w = __uint_as_float(tf32r(v.w));
            *(float4*)&xs[r][q * 4] = u;
        }
        __syncthreads();

        float acc[4][4][4];
#pragma unroll
        for (int mt = 0; mt < 4; mt++)
#pragma unroll
            for (int nt = 0; nt < 4; nt++)
#pragma unroll
                for (int c = 0; c < 4; c++) acc[mt][nt][c] = 0.0f;

#pragma unroll
        for (int ks = 0; ks < 8; ks++) {
            unsigned a[4][4];
#pragma unroll
            for (int mt = 0; mt < 4; mt++) {
                a[mt][0] = __float_as_uint(xs[mt * 16 + gid][ks * 8 + tig]);
                a[mt][1] = __float_as_uint(xs[mt * 16 + gid + 8][ks * 8 + tig]);
                a[mt][2] = __float_as_uint(xs[mt * 16 + gid][ks * 8 + tig + 4]);
                a[mt][3] = __float_as_uint(xs[mt * 16 + gid + 8][ks * 8 + tig + 4]);
            }
#pragma unroll
            for (int mt = 0; mt < 4; mt++)
#pragma unroll
                for (int nt = 0; nt < 4; nt++)
                    asm volatile(
                        "mma.sync.aligned.m16n8k8.row.col.f32.tf32.tf32.f32 "
                        "{%0,%1,%2,%3}, {%4,%5,%6,%7}, {%8,%9}, {%0,%1,%2,%3};"
                        : "+f"(acc[mt][nt][0]), "+f"(acc[mt][nt][1]),
                          "+f"(acc[mt][nt][2]), "+f"(acc[mt][nt][3])
                        : "r"(a[mt][0]), "r"(a[mt][1]), "r"(a[mt][2]), "r"(a[mt][3]),
                          "r"(B[nt][ks][0]), "r"(B[nt][ks][1]));
        }

        // epilogue: + bias, store float2 pairs
#pragma unroll
        for (int mt = 0; mt < 4; mt++) {
            size_t r0 = row0 + mt * 16 + gid;
#pragma unroll
            for (int nt = 0; nt < 4; nt++) {
                int col = cb + nt * 8 + tig * 2;
                float b0v = sbias[col], b1v = sbias[col + 1];
                *(float2*)&g_GX[r0 * 256 + col] =
                    make_float2(acc[mt][nt][0] + b0v, acc[mt][nt][1] + b1v);
                *(float2*)&g_GX[(r0 + 8) * 256 + col] =
                    make_float2(acc[mt][nt][2] + b0v, acc[mt][nt][3] + b1v);
            }
        }
        __syncthreads();
    }
}

// ---------------- batched layer-1 GEMM over all t ----------------------------
__global__ void __launch_bounds__(256) k_gemm_b(const float* __restrict__ X) {
    __shared__ __align__(16) float xs[64][64];
    __shared__ __align__(16) ull wsp[64][32];
    __shared__ float sbias[64];
    int tid = threadIdx.x;
    int t = blockIdx.y;
    int n0 = blockIdx.x * 64;

    for (int idx = tid; idx < 2048; idx += 256) {
        int k = idx >> 5, c = idx & 31;
        float2 w = *(const float2*)&g_W0s[k * 64 + c * 2];
        wsp[k][c] = pack2f(w.x, w.y);
    }
    if (tid < 64) sbias[tid] = g_bvec0[tid];
    for (int idx = tid; idx < 1024; idx += 256) {
        int r = idx >> 4, q = idx & 15;
        int n = n0 + r;
        if (n < N_NODES)
            *(float4*)&xs[r][q * 4] = *(const float4*)&X[(n * T_STEPS + t) * 64 + q * 4];
    }
    __syncthreads();

    int r0 = (tid >> 4) * 4;
    int cg = (tid & 15);
    ull acc[4][2] = {};
#pragma unroll 8
    for (int k = 0; k < 64; k++) {
        ulonglong2 wp = *(ulonglong2*)&wsp[k][cg * 2];
#pragma unroll
        for (int i = 0; i < 4; i++) {
            ull x2 = dup2f(xs[r0 + i][k]);
            acc[i][0] = ffma2(x2, wp.x, acc[i][0]);
            acc[i][1] = ffma2(x2, wp.y, acc[i][1]);
        }
    }
    int c0 = cg * 4;
#pragma unroll
    for (int i = 0; i < 4; i++) {
        int n = n0 + r0 + i;
        if (n < N_NODES) {
            float sc = g_outnorm[n];
            float2 p0 = unpack2(acc[i][0]);
            float2 p1 = unpack2(acc[i][1]);
            uint2 o;
            o.x = bf2pack(sc * (p0.x + sbias[c0 + 0]), sc * (p0.y + sbias[c0 + 1]));
            o.y = bf2pack(sc * (p1.x + sbias[c0 + 2]), sc * (p1.y + sbias[c0 + 3]));
            *(uint2*)&g_M1[(t * N_NODES + n) * 32 + (c0 >> 1)] = o;
        }
    }
}

// ---------------- gather layer1 + gelu + fused y@W1 -> m2 (bf16) -------------
__global__ void __launch_bounds__(256) k_gatherA(const float* __restrict__ W1,
                                                 const float* __restrict__ b0) {
    __shared__ __align__(16) ull sW1p[64 * 32];
    __shared__ float sY[8][64];
    int tid = threadIdx.x;
    int t = blockIdx.y;
    int lane = tid & 31, w = tid >> 5;
    for (int idx = tid; idx < 2048; idx += 256) {
        int k = idx >> 5, c = idx & 31;
        float2 ww = *(const float2*)&W1[k * 64 + c * 2];
        sW1p[idx] = pack2f(ww.x, ww.y);
    }
    __syncthreads();

    int warpg = blockIdx.x * 8 + w;
    int nwarps = gridDim.x * 8;
    float bb0 = b0[2 * lane], bb1 = b0[2 * lane + 1];
    unsigned base = (unsigned)t * N_NODES;

    for (int v = warpg; v < N_NODES; v += nwarps) {
        int s = g_rowptr[v], e = g_rowptr[v + 1];
        float a0 = 0.0f, a1 = 0.0f;
        int i = s;
        for (; i + 4 <= e; i += 4) {
            int u0 = g_csrsrc[i + 0];
            int u1 = g_csrsrc[i + 1];
            int u2 = g_csrsrc[i + 2];
            int u3 = g_csrsrc[i + 3];
            float2 m0 = bf2unpack(g_M1[(base + u0) * 32 + lane]);
            float2 m1 = bf2unpack(g_M1[(base + u1) * 32 + lane]);
            float2 m2 = bf2unpack(g_M1[(base + u2) * 32 + lane]);
            float2 m3 = bf2unpack(g_M1[(base + u3) * 32 + lane]);
            a0 += (m0.x + m1.x) + (m2.x + m3.x);
            a1 += (m0.y + m1.y) + (m2.y + m3.y);
        }
        for (; i < e; i++) {
            int u = g_csrsrc[i];
            float2 m = bf2unpack(g_M1[(base + u) * 32 + lane]);
            a0 += m.x; a1 += m.y;
        }
        float inn = g_innorm[v];
        sY[w][2 * lane]     = gelu_f(a0 * inn + bb0);
        sY[w][2 * lane + 1] = gelu_f(a1 * inn + bb1);
        __syncwarp();
        ull acc = 0ull;
#pragma unroll 8
        for (int k = 0; k < 64; k++)
            acc = ffma2(dup2f(sY[w][k]), sW1p[k * 32 + lane], acc);
        float2 p = unpack2(acc);
        float sc = g_outnorm[v];
        g_M2[(base + v) * 32 + lane] = bf2pack(sc * p.x, sc * p.y);
        __syncwarp();
    }
}

// ---------------- gather layer2 + gelu + mean -> hs ---------------------------
__global__ void __launch_bounds__(256) k_gatherB(const float* __restrict__ b1,
                                                 float* __restrict__ out) {
    int tid = threadIdx.x;
    int t = blockIdx.y;
    int lane = tid & 31;
    int warpg = blockIdx.x * 8 + (tid >> 5);
    int nwarps = gridDim.x * 8;
    float bb0 = b1[2 * lane], bb1 = b1[2 * lane + 1];
    unsigned base = (unsigned)t * N_NODES;
    float acc0t = 0.0f, acc1t = 0.0f;

    for (int v = warpg; v < N_NODES; v += nwarps) {
        int s = g_rowptr[v], e = g_rowptr[v + 1];
        float a0 = 0.0f, a1 = 0.0f;
        int i = s;
        for (; i + 4 <= e; i += 4) {
            int u0 = g_csrsrc[i + 0];
            int u1 = g_csrsrc[i + 1];
            int u2 = g_csrsrc[i + 2];
            int u3 = g_csrsrc[i + 3];
            float2 m0 = bf2unpack(g_M2[(base + u0) * 32 + lane]);
            float2 m1 = bf2unpack(g_M2[(base + u1) * 32 + lane]);
            float2 m2 = bf2unpack(g_M2[(base + u2) * 32 + lane]);
            float2 m3 = bf2unpack(g_M2[(base + u3) * 32 + lane]);
            a0 += (m0.x + m1.x) + (m2.x + m3.x);
            a1 += (m0.y + m1.y) + (m2.y + m3.y);
        }
        for (; i < e; i++) {
            int u = g_csrsrc[i];
            float2 m = bf2unpack(g_M2[(base + u) * 32 + lane]);
            a0 += m.x; a1 += m.y;
        }
        float inn = g_innorm[v];
        acc0t += gelu_f(a0 * inn + bb0);
        acc1t += gelu_f(a1 * inn + bb1);
    }
    __shared__ float red[64];
    if (tid < 64) red[tid] = 0.0f;
    __syncthreads();
    atomicAdd(&red[2 * lane + 0], acc0t);
    atomicAdd(&red[2 * lane + 1], acc1t);
    __syncthreads();
    if (tid < 64)
        atomicAdd(&out[t * 64 + tid], red[tid] * (1.0f / (float)N_NODES));
}

// ---------------- persistent recurrent LSTM (h@Whh only; x-part from GX) -----
#define LSTM_SMEM_BYTES (65536 + 8 * 2048)   // Wh2 64KB + 8 warps * 512 floats h
__global__ void __launch_bounds__(256, 1) k_lstm_all(float* __restrict__ out_ht) {
    extern __shared__ char dynsm[];
    ull* sWh = (ull*)dynsm;
    float* stage = (float*)(dynsm + 65536);

    int tid = threadIdx.x, w = tid >> 5, lane = tid & 31;
    for (int i = tid; i < 8192; i += 256) sWh[i] = g_Wh2[i];
    __syncthreads();

    float* myH = stage + w * 512;
    const int NGROUPS = N_NODES / 8;   // 6250 exact
    const float inv = 1.0f / (float)T_STEPS;

    for (;;) {
        int grp = 0;
        if (lane == 0) grp = atomicAdd(&g_wq, 1);
        grp = __shfl_sync(0xffffffffu, grp, 0);
        if (grp >= NGROUPS) break;
        int n0 = grp * 8;

        ull c2[8];
        float hs0[8], hs1[8];
#pragma unroll
        for (int i = 0; i < 8; i++) { c2[i] = 0ull; hs0[i] = 0.0f; hs1[i] = 0.0f; }
        for (int j = lane; j < 512; j += 32) myH[j] = 0.0f;
        __syncwarp();

        for (int t = 0; t < T_STEPS; t++) {
            ull acc[8][4];
#pragma unroll
            for (int i = 0; i < 8; i++) {
                const float* gx = g_GX + ((size_t)(n0 + i) * T_STEPS + t) * 256;
#pragma unroll
                for (int j = 0; j < 4; j++)
                    acc[i][j] = pack2f(gx[j * 64 + lane], gx[j * 64 + 32 + lane]);
            }

#pragma unroll 4
            for (int k = 0; k < 64; k++) {
                ull wh0 = sWh[k * 128 + lane];
                ull wh1 = sWh[k * 128 + 32 + lane];
                ull wh2v = sWh[k * 128 + 64 + lane];
                ull wh3 = sWh[k * 128 + 96 + lane];
#pragma unroll
                for (int i = 0; i < 8; i++) {
                    ull h2 = dup2f(myH[i * 64 + k]);
                    acc[i][0] = ffma2(h2, wh0, acc[i][0]);
                    acc[i][1] = ffma2(h2, wh1, acc[i][1]);
                    acc[i][2] = ffma2(h2, wh2v, acc[i][2]);
                    acc[i][3] = ffma2(h2, wh3, acc[i][3]);
                }
            }
            __syncwarp();

#pragma unroll
            for (int i = 0; i < 8; i++) {
                float2 gi = unpack2(acc[i][0]);
                float2 gf = unpack2(acc[i][1]);
                float2 gg = unpack2(acc[i][2]);
                float2 go = unpack2(acc[i][3]);
                float2 cp = unpack2(c2[i]);
                float c0 = sig_f(gf.x) * cp.x + sig_f(gi.x) * tanhf(gg.x);
                float c1 = sig_f(gf.y) * cp.y + sig_f(gi.y) * tanhf(gg.y);
                float h0 = sig_f(go.x) * tanhf(c0);
                float h1 = sig_f(go.y) * tanhf(c1);
                c2[i] = pack2f(c0, c1);
                hs0[i] += h0; hs1[i] += h1;
                myH[i * 64 + lane]      = h0;
                myH[i * 64 + lane + 32] = h1;
            }
            __syncwarp();
        }

#pragma unroll
        for (int i = 0; i < 8; i++) {
            int n = n0 + i;
            out_ht[n * 64 + lane]      = hs0[i] * inv;
            out_ht[n * 64 + lane + 32] = hs1[i] * inv;
        }
    }
}

__global__ void k_join_anchor() {}

// ---------------- launch ------------------------------------------------------
extern "C" void kernel_launch(void* const* d_in, const int* in_sizes, int n_in,
                              void* d_out, int out_size) {
    const float* h     = (const float*)d_in[0];
    const int*   src   = (const int*)d_in[1];
    const int*   dst   = (const int*)d_in[2];
    const float* gamma = (const float*)d_in[3];
    const float* beta  = (const float*)d_in[4];
    const float* W0    = (const float*)d_in[5];
    const float* b0    = (const float*)d_in[6];
    const float* W1    = (const float*)d_in[7];
    const float* b1    = (const float*)d_in[8];
    const float* Wih   = (const float*)d_in[9];
    const float* Whh   = (const float*)d_in[10];
    const float* bih   = (const float*)d_in[11];
    const float* bhh   = (const float*)d_in[12];
    float* out = (float*)d_out;
    (void)in_sizes; (void)n_in;

    cudaFuncSetAttribute(k_lstm_all, cudaFuncAttributeMaxDynamicSharedMemorySize,
                         LSTM_SMEM_BYTES);

    // ---- two-stream fork/join (fallback: single stream) ----
    cudaStream_t s1 = 0;
    cudaEvent_t eFork = 0, ePrep = 0, eJoin = 0;
    bool multi = (cudaStreamCreateWithFlags(&s1, cudaStreamNonBlocking) == cudaSuccess);
    if (multi) multi = (cudaEventCreateWithFlags(&eFork, cudaEventDisableTiming) == cudaSuccess);
    if (multi) multi = (cudaEventCreateWithFlags(&ePrep, cudaEventDisableTiming) == cudaSuccess);
    if (multi) multi = (cudaEventCreateWithFlags(&eJoin, cudaEventDisableTiming) == cudaSuccess);

    k_init<<<512, 256>>>(out, out_size);

    if (multi) multi = (cudaEventRecord(eFork, 0) == cudaSuccess);
    if (multi) multi = (cudaStreamWaitEvent(s1, eFork, 0) == cudaSuccess);
    cudaStream_t sg = multi ? s1 : (cudaStream_t)0;

    // stream 0: BN + folds + tensor-core GX + persistent recurrent LSTM
    k_bnstats<<<1184, 256>>>((const float4*)h);
    k_prep1<<<1, 256>>>(gamma, beta, W0);
    if (multi) cudaEventRecord(ePrep, 0);      // spatial needs g_W0s / g_bvec0
    k_prepW<<<64, 256>>>(Wih);
    k_prep3<<<1, 256>>>(Wih, bih, bhh);
    k_prep2<<<32, 256>>>(Whh);
    k_gx<<<148, 256>>>(h);
    k_lstm_all<<<148, 256, LSTM_SMEM_BYTES>>>(out + T_STEPS * 64);

    // sg: graph structure, then batched spatial stages
    k_deg<<<800, 256, 0, sg>>>(src, dst);
    k_norm<<<128, 256, 0, sg>>>();
    k_scan<<<1, 1024, 0, sg>>>();
    k_csr<<<800, 256, 0, sg>>>(src, dst);
    if (multi) cudaStreamWaitEvent(sg, ePrep, 0);

    dim3 ggemm((N_NODES + 63) / 64, T_STEPS);
    dim3 gA(104, T_STEPS);
    dim3 gB(52, T_STEPS);
    k_gemm_b<<<ggemm, 256, 0, sg>>>(h);
    k_gatherA<<<gA, 256, 0, sg>>>(W1, b0);
    k_gatherB<<<gB, 256, 0, sg>>>(b1, out);

    if (multi) {
        cudaEventRecord(eJoin, sg);
        cudaStreamWaitEvent(0, eJoin, 0);
        k_join_anchor<<<1, 1, 0, 0>>>();
    }
}

// round 6
// speedup vs baseline: 1.8223x; 1.0070x over previous
#include <cuda_runtime.h>
#include <cuda_bf16.h>
#include <math.h>
#include <stdint.h>

#define N_NODES 50000
#define T_STEPS 24
#define E_EDGES 800000
#define NT_ROWS (N_NODES * T_STEPS)

typedef unsigned long long ull;

// ---------------- f32x2 / bf16 packed helpers -------------------------------
__device__ __forceinline__ ull ffma2(ull a, ull b, ull c) {
    ull d;
    asm("fma.rn.f32x2 %0, %1, %2, %3;" : "=l"(d) : "l"(a), "l"(b), "l"(c));
    return d;
}
__device__ __forceinline__ ull dup2f(float x) {
    ull r; asm("mov.b64 %0, {%1, %1};" : "=l"(r) : "f"(x)); return r;
}
__device__ __forceinline__ ull pack2f(float x, float y) {
    ull r; asm("mov.b64 %0, {%1, %2};" : "=l"(r) : "f"(x), "f"(y)); return r;
}
__device__ __forceinline__ float2 unpack2(ull v) {
    float2 r; asm("mov.b64 {%0, %1}, %2;" : "=f"(r.x), "=f"(r.y) : "l"(v)); return r;
}
__device__ __forceinline__ unsigned bf2pack(float x, float y) {
    __nv_bfloat162 b = __float22bfloat162_rn(make_float2(x, y));
    return *(unsigned*)&b;
}
__device__ __forceinline__ float2 bf2unpack(unsigned u) {
    __nv_bfloat162 b = *(__nv_bfloat162*)&u;
    return __bfloat1622float2(b);
}
__device__ __forceinline__ unsigned tf32r(float f) {
    unsigned u; asm("cvt.rna.tf32.f32 %0, %1;" : "=r"(u) : "f"(f)); return u;
}

// ---------------- scratch (device globals) ----------------------------------
__device__ float g_sum[64];
__device__ float g_sumsq[64];
__device__ float g_a[64];
__device__ float g_bsh[64];
__device__ float g_W0s[64 * 64];
__device__ float g_bvec0[64];
__device__ ull   g_Wh2[64 * 128];
__device__ float g_gbias[256];
__device__ unsigned g_Wg[256 * 64];               // tf32 bits of a*Wih, [g][k]
__device__ float g_outnorm[N_NODES];
__device__ float g_innorm[N_NODES];
__device__ int   g_degout[N_NODES];
__device__ int   g_degin[N_NODES];
__device__ int   g_rowptr[N_NODES + 1];
__device__ int   g_cursor[N_NODES];
__device__ int   g_csrsrc[E_EDGES];
__device__ unsigned g_M1[T_STEPS * N_NODES * 32];
__device__ unsigned g_M2[T_STEPS * N_NODES * 32];
__device__ int   g_wq;

__device__ __forceinline__ float gelu_f(float x) {
    return 0.5f * x * (1.0f + erff(x * 0.70710678118654752440f));
}
__device__ __forceinline__ float sig_f(float x) {
    return 1.0f / (1.0f + expf(-x));
}

// ---------------- init -------------------------------------------------------
__global__ void k_init(float* out, int out_n) {
    int i = blockIdx.x * blockDim.x + threadIdx.x;
    int stride = gridDim.x * blockDim.x;
    for (int j = i; j < out_n; j += stride) out[j] = 0.0f;
    for (int j = i; j < N_NODES; j += stride) { g_degout[j] = 0; g_degin[j] = 0; }
    if (i < 64) { g_sum[i] = 0.0f; g_sumsq[i] = 0.0f; }
    if (i == 0) g_wq = 0;
}

// ---------------- BN stats ---------------------------------------------------
__global__ void k_bnstats(const float4* __restrict__ h4) {
    __shared__ float ss[64], sq[64];
    int tid = threadIdx.x;
    if (tid < 64) { ss[tid] = 0.0f; sq[tid] = 0.0f; }
    __syncthreads();
    const int total4 = NT_ROWS * 16;
    float4 s = make_float4(0, 0, 0, 0);
    float4 q = make_float4(0, 0, 0, 0);
    for (int i = blockIdx.x * blockDim.x + tid; i < total4; i += gridDim.x * blockDim.x) {
        float4 v = h4[i];
        s.x += v.x; s.y += v.y; s.z += v.z; s.w += v.w;
        q.x += v.x * v.x; q.y += v.y * v.y; q.z += v.z * v.z; q.w += v.w * v.w;
    }
    int c = (tid & 15) * 4;
    atomicAdd(&ss[c + 0], s.x); atomicAdd(&ss[c + 1], s.y);
    atomicAdd(&ss[c + 2], s.z); atomicAdd(&ss[c + 3], s.w);
    atomicAdd(&sq[c + 0], q.x); atomicAdd(&sq[c + 1], q.y);
    atomicAdd(&sq[c + 2], q.z); atomicAdd(&sq[c + 3], q.w);
    __syncthreads();
    if (tid < 64) {
        atomicAdd(&g_sum[tid], ss[tid]);
        atomicAdd(&g_sumsq[tid], sq[tid]);
    }
}

// ---------------- BN finalize + fold into W0 --------------------------------
__global__ void k_prep1(const float* __restrict__ gamma, const float* __restrict__ beta,
                        const float* __restrict__ W0) {
    __shared__ float sa[64], sb[64];
    int tid = threadIdx.x;  // 256
    if (tid < 64) {
        float mu  = g_sum[tid]   * (1.0f / (float)NT_ROWS);
        float var = g_sumsq[tid] * (1.0f / (float)NT_ROWS) - mu * mu;
        float a = gamma[tid] * rsqrtf(var + 1e-5f);
        sa[tid] = a;
        sb[tid] = beta[tid] - mu * a;
        g_a[tid] = a; g_bsh[tid] = sb[tid];
    }
    __syncthreads();
    for (int idx = tid; idx < 4096; idx += 256) {
        int k = idx >> 6;
        g_W0s[idx] = sa[k] * W0[idx];
    }
    if (tid < 64) {
        float acc = 0.0f;
        for (int k = 0; k < 64; k++) acc += sb[k] * W0[k * 64 + tid];
        g_bvec0[tid] = acc;
    }
}

// ---------------- pack Whh pairs ---------------------------------------------
__global__ void k_prep2(const float* __restrict__ Whh) {
    int idx = blockIdx.x * blockDim.x + threadIdx.x;   // 0..8191
    if (idx >= 8192) return;
    int k = idx >> 7, r = idx & 127;
    int j = r >> 5, l = r & 31;
    int gA = j * 64 + l, gB = gA + 32;
    g_Wh2[idx] = pack2f(Whh[gA * 64 + k], Whh[gB * 64 + k]);
}

// ---------------- gate bias (fp32) -------------------------------------------
__global__ void k_prep3(const float* __restrict__ Wih,
                        const float* __restrict__ bih, const float* __restrict__ bhh) {
    int g = threadIdx.x;  // 256
    float acc = bih[g] + bhh[g];
    for (int k = 0; k < 64; k++) acc += g_bsh[k] * Wih[g * 64 + k];
    g_gbias[g] = acc;
}

// ---------------- tf32 weight tile: (a*Wih)[256 x 64] ------------------------
__global__ void k_prepW(const float* __restrict__ Wih) {
    int idx = blockIdx.x * blockDim.x + threadIdx.x;   // 0..16383
    if (idx >= 16384) return;
    int g = idx >> 6, k = idx & 63;
    g_Wg[idx] = tf32r(g_a[k] * Wih[g * 64 + k]);
}

// ---------------- degrees / norms / CSR --------------------------------------
__global__ void k_deg(const int* __restrict__ src, const int* __restrict__ dst) {
    for (int e = blockIdx.x * blockDim.x + threadIdx.x; e < E_EDGES;
         e += gridDim.x * blockDim.x) {
        atomicAdd(&g_degout[src[e]], 1);
        atomicAdd(&g_degin[dst[e]], 1);
    }
}

__global__ void k_norm() {
    for (int n = blockIdx.x * blockDim.x + threadIdx.x; n < N_NODES;
         n += gridDim.x * blockDim.x) {
        g_outnorm[n] = rsqrtf(fmaxf((float)g_degout[n], 1.0f));
        g_innorm[n]  = rsqrtf(fmaxf((float)g_degin[n], 1.0f));
    }
}

__global__ void k_scan() {
    __shared__ int s[1024];
    const int CH = 49;
    int tid = threadIdx.x;
    int base = tid * CH;
    int tot = 0;
    for (int i = 0; i < CH; i++) {
        int idx = base + i;
        if (idx < N_NODES) tot += g_degin[idx];
    }
    s[tid] = tot;
    __syncthreads();
    for (int off = 1; off < 1024; off <<= 1) {
        int v = (tid >= off) ? s[tid - off] : 0;
        __syncthreads();
        s[tid] += v;
        __syncthreads();
    }
    int run = (tid > 0) ? s[tid - 1] : 0;
    for (int i = 0; i < CH; i++) {
        int idx = base + i;
        if (idx < N_NODES) {
            g_rowptr[idx] = run;
            g_cursor[idx] = run;
            run += g_degin[idx];
        } else if (idx == N_NODES) {
            g_rowptr[idx] = run;
        }
    }
}

__global__ void k_csr(const int* __restrict__ src, const int* __restrict__ dst) {
    for (int e = blockIdx.x * blockDim.x + threadIdx.x; e < E_EDGES;
         e += gridDim.x * blockDim.x) {
        int pos = atomicAdd(&g_cursor[dst[e]], 1);
        g_csrsrc[pos] = src[e];
    }
}

// ---------------- batched layer-1 GEMM over all t ----------------------------
__global__ void __launch_bounds__(256) k_gemm_b(const float* __restrict__ X) {
    __shared__ __align__(16) float xs[64][64];
    __shared__ __align__(16) ull wsp[64][32];
    __shared__ float sbias[64];
    int tid = threadIdx.x;
    int t = blockIdx.y;
    int n0 = blockIdx.x * 64;

    for (int idx = tid; idx < 2048; idx += 256) {
        int k = idx >> 5, c = idx & 31;
        float2 w = *(const float2*)&g_W0s[k * 64 + c * 2];
        wsp[k][c] = pack2f(w.x, w.y);
    }
    if (tid < 64) sbias[tid] = g_bvec0[tid];
    for (int idx = tid; idx < 1024; idx += 256) {
        int r = idx >> 4, q = idx & 15;
        int n = n0 + r;
        if (n < N_NODES)
            *(float4*)&xs[r][q * 4] = *(const float4*)&X[(n * T_STEPS + t) * 64 + q * 4];
    }
    __syncthreads();

    int r0 = (tid >> 4) * 4;
    int cg = (tid & 15);
    ull acc[4][2] = {};
#pragma unroll 8
    for (int k = 0; k < 64; k++) {
        ulonglong2 wp = *(ulonglong2*)&wsp[k][cg * 2];
#pragma unroll
        for (int i = 0; i < 4; i++) {
            ull x2 = dup2f(xs[r0 + i][k]);
            acc[i][0] = ffma2(x2, wp.x, acc[i][0]);
            acc[i][1] = ffma2(x2, wp.y, acc[i][1]);
        }
    }
    int c0 = cg * 4;
#pragma unroll
    for (int i = 0; i < 4; i++) {
        int n = n0 + r0 + i;
        if (n < N_NODES) {
            float sc = g_outnorm[n];
            float2 p0 = unpack2(acc[i][0]);
            float2 p1 = unpack2(acc[i][1]);
            uint2 o;
            o.x = bf2pack(sc * (p0.x + sbias[c0 + 0]), sc * (p0.y + sbias[c0 + 1]));
            o.y = bf2pack(sc * (p1.x + sbias[c0 + 2]), sc * (p1.y + sbias[c0 + 3]));
            *(uint2*)&g_M1[(t * N_NODES + n) * 32 + (c0 >> 1)] = o;
        }
    }
}

// ---------------- gather layer1 + gelu + fused y@W1 -> m2 (bf16) -------------
__global__ void __launch_bounds__(256) k_gatherA(const float* __restrict__ W1,
                                                 const float* __restrict__ b0) {
    __shared__ __align__(16) ull sW1p[64 * 32];
    __shared__ float sY[8][64];
    int tid = threadIdx.x;
    int t = blockIdx.y;
    int lane = tid & 31, w = tid >> 5;
    for (int idx = tid; idx < 2048; idx += 256) {
        int k = idx >> 5, c = idx & 31;
        float2 ww = *(const float2*)&W1[k * 64 + c * 2];
        sW1p[idx] = pack2f(ww.x, ww.y);
    }
    __syncthreads();

    int warpg = blockIdx.x * 8 + w;
    int nwarps = gridDim.x * 8;
    float bb0 = b0[2 * lane], bb1 = b0[2 * lane + 1];
    unsigned base = (unsigned)t * N_NODES;

    for (int v = warpg; v < N_NODES; v += nwarps) {
        int s = g_rowptr[v], e = g_rowptr[v + 1];
        float a0 = 0.0f, a1 = 0.0f;
        int i = s;
        for (; i + 4 <= e; i += 4) {
            int u0 = g_csrsrc[i + 0];
            int u1 = g_csrsrc[i + 1];
            int u2 = g_csrsrc[i + 2];
            int u3 = g_csrsrc[i + 3];
            float2 m0 = bf2unpack(g_M1[(base + u0) * 32 + lane]);
            float2 m1 = bf2unpack(g_M1[(base + u1) * 32 + lane]);
            float2 m2 = bf2unpack(g_M1[(base + u2) * 32 + lane]);
            float2 m3 = bf2unpack(g_M1[(base + u3) * 32 + lane]);
            a0 += (m0.x + m1.x) + (m2.x + m3.x);
            a1 += (m0.y + m1.y) + (m2.y + m3.y);
        }
        for (; i < e; i++) {
            int u = g_csrsrc[i];
            float2 m = bf2unpack(g_M1[(base + u) * 32 + lane]);
            a0 += m.x; a1 += m.y;
        }
        float inn = g_innorm[v];
        sY[w][2 * lane]     = gelu_f(a0 * inn + bb0);
        sY[w][2 * lane + 1] = gelu_f(a1 * inn + bb1);
        __syncwarp();
        ull acc = 0ull;
#pragma unroll 8
        for (int k = 0; k < 64; k++)
            acc = ffma2(dup2f(sY[w][k]), sW1p[k * 32 + lane], acc);
        float2 p = unpack2(acc);
        float sc = g_outnorm[v];
        g_M2[(base + v) * 32 + lane] = bf2pack(sc * p.x, sc * p.y);
        __syncwarp();
    }
}

// ---------------- gather layer2 + gelu + mean -> hs ---------------------------
__global__ void __launch_bounds__(256) k_gatherB(const float* __restrict__ b1,
                                                 float* __restrict__ out) {
    int tid = threadIdx.x;
    int t = blockIdx.y;
    int lane = tid & 31;
    int warpg = blockIdx.x * 8 + (tid >> 5);
    int nwarps = gridDim.x * 8;
    float bb0 = b1[2 * lane], bb1 = b1[2 * lane + 1];
    unsigned base = (unsigned)t * N_NODES;
    float acc0t = 0.0f, acc1t = 0.0f;

    for (int v = warpg; v < N_NODES; v += nwarps) {
        int s = g_rowptr[v], e = g_rowptr[v + 1];
        float a0 = 0.0f, a1 = 0.0f;
        int i = s;
        for (; i + 4 <= e; i += 4) {
            int u0 = g_csrsrc[i + 0];
            int u1 = g_csrsrc[i + 1];
            int u2 = g_csrsrc[i + 2];
            int u3 = g_csrsrc[i + 3];
            float2 m0 = bf2unpack(g_M2[(base + u0) * 32 + lane]);
            float2 m1 = bf2unpack(g_M2[(base + u1) * 32 + lane]);
            float2 m2 = bf2unpack(g_M2[(base + u2) * 32 + lane]);
            float2 m3 = bf2unpack(g_M2[(base + u3) * 32 + lane]);
            a0 += (m0.x + m1.x) + (m2.x + m3.x);
            a1 += (m0.y + m1.y) + (m2.y + m3.y);
        }
        for (; i < e; i++) {
            int u = g_csrsrc[i];
            float2 m = bf2unpack(g_M2[(base + u) * 32 + lane]);
            a0 += m.x; a1 += m.y;
        }
        float inn = g_innorm[v];
        acc0t += gelu_f(a0 * inn + bb0);
        acc1t += gelu_f(a1 * inn + bb1);
    }
    __shared__ float red[64];
    if (tid < 64) red[tid] = 0.0f;
    __syncthreads();
    atomicAdd(&red[2 * lane + 0], acc0t);
    atomicAdd(&red[2 * lane + 1], acc1t);
    __syncthreads();
    if (tid < 64)
        atomicAdd(&out[t * 64 + tid], red[tid] * (1.0f / (float)N_NODES));
}

// ---------------- fused persistent LSTM ---------------------------------------
// Block owns 64 nodes for all T steps. Per step:
//  1) stage x tile (tf32) into smem
//  2) tensor-core mma: gates_x = x @ (a*Wih)^T + bias  -> smem (no global GX!)
//  3) fp32 FFMA2 recurrent part h@Whh^T, gate math, update h/c
// smem: Wh 64K | gates 64K | xs 17K(pad 68) | hstage 16K | bias 1K = 165888 B
#define LSTM_SMEM_BYTES (65536 + 65536 + 17408 + 16384 + 1024)
__global__ void __launch_bounds__(256, 1) k_lstm_fused(
    const float* __restrict__ h_all, float* __restrict__ out_ht) {
    extern __shared__ char dynsm[];
    ull*   sWh   = (ull*)dynsm;                       // [64][128]
    float* gxs   = (float*)(dynsm + 65536);           // [64][256]
    float* xs    = (float*)(dynsm + 131072);          // [64][68]
    float* stage = (float*)(dynsm + 148480);          // 8 warps * 512
    float* sbias = (float*)(dynsm + 164864);          // [256]
    __shared__ int sgrp;

    int tid = threadIdx.x, w = tid >> 5, lane = tid & 31;
    int gid = lane >> 2, tig = lane & 3;
    int cb = w * 32;

    for (int i = tid; i < 8192; i += 256) sWh[i] = g_Wh2[i];
    sbias[tid] = g_gbias[tid];

    // persistent B fragments: warp w covers gate cols cb..cb+31
    unsigned B[4][8][2];
#pragma unroll
    for (int nt = 0; nt < 4; nt++) {
        int col = cb + nt * 8 + gid;
#pragma unroll
        for (int ks = 0; ks < 8; ks++) {
            B[nt][ks][0] = g_Wg[col * 64 + ks * 8 + tig];
            B[nt][ks][1] = g_Wg[col * 64 + ks * 8 + tig + 4];
        }
    }
    __syncthreads();

    float* myH = stage + w * 512;
    const int NGROUPS = (N_NODES + 63) / 64;   // 782
    const float inv = 1.0f / (float)T_STEPS;

    for (;;) {
        if (tid == 0) sgrp = atomicAdd(&g_wq, 1);
        __syncthreads();
        int grp = sgrp;
        if (grp >= NGROUPS) break;
        int n0 = grp * 64;
        int nw0 = n0 + w * 8;     // this warp's 8 nodes

        ull c2[8];
        float hs0[8], hs1[8];
#pragma unroll
        for (int i = 0; i < 8; i++) { c2[i] = 0ull; hs0[i] = 0.0f; hs1[i] = 0.0f; }
        for (int j = lane; j < 512; j += 32) myH[j] = 0.0f;

        for (int t = 0; t < T_STEPS; t++) {
            // ---- stage x tile (tf32-rounded) ----
#pragma unroll
            for (int i = 0; i < 4; i++) {
                int idx = tid + i * 256;            // 0..1023 float4 slots
                int r = idx >> 4, q = idx & 15;
                int n = n0 + r;
                float4 v = make_float4(0, 0, 0, 0);
                if (n < N_NODES)
                    v = *(const float4*)&h_all[((size_t)n * T_STEPS + t) * 64 + q * 4];
                float4 u;
                u.x = __uint_as_float(tf32r(v.x));
                u.y = __uint_as_float(tf32r(v.y));
                u.z = __uint_as_float(tf32r(v.z));
                u.w = __uint_as_float(tf32r(v.w));
                *(float4*)&xs[r * 68 + q * 4] = u;
            }
            __syncthreads();   // xs ready; prev recurrent done (gxs free)

            // ---- tensor-core x-projection ----
            float acc[4][4][4];
#pragma unroll
            for (int mt = 0; mt < 4; mt++)
#pragma unroll
                for (int nt = 0; nt < 4; nt++)
#pragma unroll
                    for (int c = 0; c < 4; c++) acc[mt][nt][c] = 0.0f;

#pragma unroll
            for (int ks = 0; ks < 8; ks++) {
                unsigned a[4][4];
#pragma unroll
                for (int mt = 0; mt < 4; mt++) {
                    a[mt][0] = __float_as_uint(xs[(mt * 16 + gid) * 68 + ks * 8 + tig]);
                    a[mt][1] = __float_as_uint(xs[(mt * 16 + gid + 8) * 68 + ks * 8 + tig]);
                    a[mt][2] = __float_as_uint(xs[(mt * 16 + gid) * 68 + ks * 8 + tig + 4]);
                    a[mt][3] = __float_as_uint(xs[(mt * 16 + gid + 8) * 68 + ks * 8 + tig + 4]);
                }
#pragma unroll
                for (int mt = 0; mt < 4; mt++)
#pragma unroll
                    for (int nt = 0; nt < 4; nt++)
                        asm volatile(
                            "mma.sync.aligned.m16n8k8.row.col.f32.tf32.tf32.f32 "
                            "{%0,%1,%2,%3}, {%4,%5,%6,%7}, {%8,%9}, {%0,%1,%2,%3};"
                            : "+f"(acc[mt][nt][0]), "+f"(acc[mt][nt][1]),
                              "+f"(acc[mt][nt][2]), "+f"(acc[mt][nt][3])
                            : "r"(a[mt][0]), "r"(a[mt][1]), "r"(a[mt][2]), "r"(a[mt][3]),
                              "r"(B[nt][ks][0]), "r"(B[nt][ks][1]));
            }
            // epilogue: + bias -> gxs
#pragma unroll
            for (int mt = 0; mt < 4; mt++) {
                int r0 = mt * 16 + gid;
#pragma unroll
                for (int nt = 0; nt < 4; nt++) {
                    int col = cb + nt * 8 + tig * 2;
                    float b0v = sbias[col], b1v = sbias[col + 1];
                    *(float2*)&gxs[r0 * 256 + col] =
                        make_float2(acc[mt][nt][0] + b0v, acc[mt][nt][1] + b1v);
                    *(float2*)&gxs[(r0 + 8) * 256 + col] =
                        make_float2(acc[mt][nt][2] + b0v, acc[mt][nt][3] + b1v);
                }
            }
            __syncthreads();   // gxs ready

            // ---- fp32 recurrent part ----
            ull racc[8][4];
#pragma unroll
            for (int i = 0; i < 8; i++) {
                const float* gx = &gxs[(w * 8 + i) * 256];
#pragma unroll
                for (int j = 0; j < 4; j++)
                    racc[i][j] = pack2f(gx[j * 64 + lane], gx[j * 64 + 32 + lane]);
            }

#pragma unroll 4
            for (int k = 0; k < 64; k++) {
                ull wh0 = sWh[k * 128 + lane];
                ull wh1 = sWh[k * 128 + 32 + lane];
                ull wh2v = sWh[k * 128 + 64 + lane];
                ull wh3 = sWh[k * 128 + 96 + lane];
#pragma unroll
                for (int i = 0; i < 8; i++) {
                    ull h2 = dup2f(myH[i * 64 + k]);
                    racc[i][0] = ffma2(h2, wh0, racc[i][0]);
                    racc[i][1] = ffma2(h2, wh1, racc[i][1]);
                    racc[i][2] = ffma2(h2, wh2v, racc[i][2]);
                    racc[i][3] = ffma2(h2, wh3, racc[i][3]);
                }
            }
            __syncwarp();

#pragma unroll
            for (int i = 0; i < 8; i++) {
                float2 gi = unpack2(racc[i][0]);
                float2 gf = unpack2(racc[i][1]);
                float2 gg = unpack2(racc[i][2]);
                float2 go = unpack2(racc[i][3]);
                float2 cp = unpack2(c2[i]);
                float c0 = sig_f(gf.x) * cp.x + sig_f(gi.x) * tanhf(gg.x);
                float c1 = sig_f(gf.y) * cp.y + sig_f(gi.y) * tanhf(gg.y);
                float h0 = sig_f(go.x) * tanhf(c0);
                float h1 = sig_f(go.y) * tanhf(c1);
                c2[i] = pack2f(c0, c1);
                hs0[i] += h0; hs1[i] += h1;
                myH[i * 64 + lane]      = h0;
                myH[i * 64 + lane + 32] = h1;
            }
            __syncwarp();
        }

#pragma unroll
        for (int i = 0; i < 8; i++) {
            int n = nw0 + i;
            if (n < N_NODES) {
                out_ht[n * 64 + lane]      = hs0[i] * inv;
                out_ht[n * 64 + lane + 32] = hs1[i] * inv;
            }
        }
        __syncthreads();   // all warps done with gxs/xs before next group
    }
}

__global__ void k_join_anchor() {}

// ---------------- launch ------------------------------------------------------
extern "C" void kernel_launch(void* const* d_in, const int* in_sizes, int n_in,
                              void* d_out, int out_size) {
    const float* h     = (const float*)d_in[0];
    const int*   src   = (const int*)d_in[1];
    const int*   dst   = (const int*)d_in[2];
    const float* gamma = (const float*)d_in[3];
    const float* beta  = (const float*)d_in[4];
    const float* W0    = (const float*)d_in[5];
    const float* b0    = (const float*)d_in[6];
    const float* W1    = (const float*)d_in[7];
    const float* b1    = (const float*)d_in[8];
    const float* Wih   = (const float*)d_in[9];
    const float* Whh   = (const float*)d_in[10];
    const float* bih   = (const float*)d_in[11];
    const float* bhh   = (const float*)d_in[12];
    float* out = (float*)d_out;
    (void)in_sizes; (void)n_in;

    cudaFuncSetAttribute(k_lstm_fused, cudaFuncAttributeMaxDynamicSharedMemorySize,
                         LSTM_SMEM_BYTES);

    // ---- two-stream fork/join (fallback: single stream) ----
    cudaStream_t s1 = 0;
    cudaEvent_t eFork = 0, ePrep = 0, eJoin = 0;
    bool multi = (cudaStreamCreateWithFlags(&s1, cudaStreamNonBlocking) == cudaSuccess);
    if (multi) multi = (cudaEventCreateWithFlags(&eFork, cudaEventDisableTiming) == cudaSuccess);
    if (multi) multi = (cudaEventCreateWithFlags(&ePrep, cudaEventDisableTiming) == cudaSuccess);
    if (multi) multi = (cudaEventCreateWithFlags(&eJoin, cudaEventDisableTiming) == cudaSuccess);

    k_init<<<512, 256>>>(out, out_size);

    if (multi) multi = (cudaEventRecord(eFork, 0) == cudaSuccess);
    if (multi) multi = (cudaStreamWaitEvent(s1, eFork, 0) == cudaSuccess);
    cudaStream_t sg = multi ? s1 : (cudaStream_t)0;

    // stream 0: BN + folds + fused tensor/FFMA LSTM
    k_bnstats<<<1184, 256>>>((const float4*)h);
    k_prep1<<<1, 256>>>(gamma, beta, W0);
    if (multi) cudaEventRecord(ePrep, 0);      // spatial needs g_W0s / g_bvec0
    k_prepW<<<64, 256>>>(Wih);
    k_prep3<<<1, 256>>>(Wih, bih, bhh);
    k_prep2<<<32, 256>>>(Whh);
    k_lstm_fused<<<148, 256, LSTM_SMEM_BYTES>>>(h, out + T_STEPS * 64);

    // sg: graph structure, then batched spatial stages
    k_deg<<<800, 256, 0, sg>>>(src, dst);
    k_norm<<<128, 256, 0, sg>>>();
    k_scan<<<1, 1024, 0, sg>>>();
    k_csr<<<800, 256, 0, sg>>>(src, dst);
    if (multi) cudaStreamWaitEvent(sg, ePrep, 0);

    dim3 ggemm((N_NODES + 63) / 64, T_STEPS);
    dim3 gA(104, T_STEPS);
    dim3 gB(52, T_STEPS);
    k_gemm_b<<<ggemm, 256, 0, sg>>>(h);
    k_gatherA<<<gA, 256, 0, sg>>>(W1, b0);
    k_gatherB<<<gB, 256, 0, sg>>>(b1, out);

    if (multi) {
        cudaEventRecord(eJoin, sg);
        cudaStreamWaitEvent(0, eJoin, 0);
        k_join_anchor<<<1, 1, 0, 0>>>();
    }
}